// round 4
// baseline (speedup 1.0000x reference)
#include <cuda_runtime.h>
#include <cuda_fp16.h>
#include <math.h>

#define N_NODES 100000
#define N_EDGES 1600000
#define HID 128
#define NGRAPH 64
#define ETILE 64
#define NTILES (N_EDGES / ETILE)
#define SCAN_B 512
#define SCAN_NB ((N_NODES + SCAN_B - 1) / SCAN_B)   // 196

// ---------------- device scratch ----------------
__device__ float  g_h[N_NODES * HID];
__device__ __half g_hh[N_NODES * HID];     // fp16 mirror of h for mma
__device__ __half g_PA[N_NODES * 256];     // dst-parts [f|s] (+bias)
__device__ __half g_PB[N_NODES * 256];     // src-parts
__device__ float  g_agg[N_NODES * HID];
__device__ float  g_pool[NGRAPH * HID + NGRAPH];
// CSR (sorted-by-dst edge structure)
__device__ int    g_deg[N_NODES];
__device__ int    g_cursor[N_NODES];
__device__ int    g_part[256];
__device__ int    g_srcs[N_EDGES];
__device__ int    g_dsts[N_EDGES];
__device__ __half g_eas[(size_t)N_EDGES * 32];

// ---------------- helpers ----------------
__device__ __forceinline__ float sigmoidf_(float x) { return 1.0f / (1.0f + __expf(-x)); }
__device__ __forceinline__ float softplusf_(float x) {
    return fmaxf(x, 0.0f) + __logf(1.0f + __expf(-fabsf(x)));
}
__device__ __forceinline__ void red4(float* p, float4 v) {
    asm volatile("red.global.add.v4.f32 [%0], {%1,%2,%3,%4};"
                 :: "l"(p), "f"(v.x), "f"(v.y), "f"(v.z), "f"(v.w) : "memory");
}
__device__ __forceinline__ void mma_f16(float d[4],
                                        unsigned a0, unsigned a1, unsigned a2, unsigned a3,
                                        unsigned b0, unsigned b1) {
    asm volatile("mma.sync.aligned.m16n8k16.row.col.f32.f16.f16.f32 "
                 "{%0,%1,%2,%3}, {%4,%5,%6,%7}, {%8,%9}, {%0,%1,%2,%3};\n"
                 : "+f"(d[0]), "+f"(d[1]), "+f"(d[2]), "+f"(d[3])
                 : "r"(a0), "r"(a1), "r"(a2), "r"(a3), "r"(b0), "r"(b1));
}

// ---------------- zero kernels ----------------
__global__ void k_zero(float* __restrict__ p, int n) {
    int i = blockIdx.x * blockDim.x + threadIdx.x;
    int s = gridDim.x * blockDim.x;
    for (; i < n; i += s) p[i] = 0.0f;
}
__global__ void k_zero_int(int* __restrict__ p, int n) {
    int i = blockIdx.x * blockDim.x + threadIdx.x;
    int s = gridDim.x * blockDim.x;
    for (; i < n; i += s) p[i] = 0;
}

// ---------------- CSR build ----------------
__global__ void k_hist(const int* __restrict__ ei, int* __restrict__ deg) {
    int e = blockIdx.x * blockDim.x + threadIdx.x;
    if (e < N_EDGES) atomicAdd(&deg[ei[N_EDGES + e]], 1);
}
__global__ void k_scan_a(const int* __restrict__ deg, int* __restrict__ cursor,
                         int* __restrict__ part) {
    __shared__ int s[SCAN_B];
    int i = blockIdx.x * SCAN_B + threadIdx.x;
    int v = (i < N_NODES) ? deg[i] : 0;
    s[threadIdx.x] = v;
    __syncthreads();
    for (int off = 1; off < SCAN_B; off <<= 1) {
        int t = (threadIdx.x >= off) ? s[threadIdx.x - off] : 0;
        __syncthreads();
        s[threadIdx.x] += t;
        __syncthreads();
    }
    if (i < N_NODES) cursor[i] = s[threadIdx.x] - v;   // exclusive within block
    if (threadIdx.x == SCAN_B - 1) part[blockIdx.x] = s[threadIdx.x];
}
__global__ void k_scan_b(int* __restrict__ part, int nb) {
    __shared__ int s[256];
    int v = (threadIdx.x < nb) ? part[threadIdx.x] : 0;
    s[threadIdx.x] = v;
    __syncthreads();
    for (int off = 1; off < 256; off <<= 1) {
        int t = (threadIdx.x >= off) ? s[threadIdx.x - off] : 0;
        __syncthreads();
        s[threadIdx.x] += t;
        __syncthreads();
    }
    if (threadIdx.x < nb) part[threadIdx.x] = s[threadIdx.x] - v;  // exclusive
}
__global__ void k_scan_c(int* __restrict__ cursor, const int* __restrict__ part) {
    int i = blockIdx.x * SCAN_B + threadIdx.x;
    if (i < N_NODES) cursor[i] += part[blockIdx.x];
}
__global__ void k_csr(const int* __restrict__ ei, const float* __restrict__ ea,
                      int* __restrict__ cursor,
                      int* __restrict__ srcs, int* __restrict__ dsts,
                      __half* __restrict__ eas) {
    int e = blockIdx.x * blockDim.x + threadIdx.x;
    if (e >= N_EDGES) return;
    int src = ei[e];
    int dst = ei[N_EDGES + e];
    int pos = atomicAdd(&cursor[dst], 1);
    srcs[pos] = src;
    dsts[pos] = dst;
    const float4* s = (const float4*)&ea[(size_t)e * 32];
    __half* d = &eas[(size_t)pos * 32];
#pragma unroll
    for (int j = 0; j < 8; j++) {
        float4 v = s[j];
        *(half2*)&d[j * 4]     = __floats2half2_rn(v.x, v.y);
        *(half2*)&d[j * 4 + 2] = __floats2half2_rn(v.z, v.w);
    }
}

// ---------------- conv1 (C=3) ----------------
__global__ void k_conv1(const float* __restrict__ x, const int* __restrict__ ei,
                        const float* __restrict__ ea,
                        const float* __restrict__ Wf, const float* __restrict__ bf,
                        const float* __restrict__ Ws, const float* __restrict__ bs,
                        float* __restrict__ agg) {
    __shared__ float sWf[38 * 3], sWs[38 * 3], sbf[3], sbs[3];
    int t = threadIdx.x;
    if (t < 114) { sWf[t] = Wf[t]; sWs[t] = Ws[t]; }
    if (t < 3)   { sbf[t] = bf[t]; sbs[t] = bs[t]; }
    __syncthreads();
    int e = blockIdx.x * blockDim.x + t;
    if (e >= N_EDGES) return;
    int src = ei[e];
    int dst = ei[N_EDGES + e];
    float z[38];
    z[0] = x[dst * 3 + 0]; z[1] = x[dst * 3 + 1]; z[2] = x[dst * 3 + 2];
    z[3] = x[src * 3 + 0]; z[4] = x[src * 3 + 1]; z[5] = x[src * 3 + 2];
#pragma unroll
    for (int k = 0; k < 32; k++) z[6 + k] = ea[(size_t)e * 32 + k];
#pragma unroll
    for (int c = 0; c < 3; c++) {
        float lf = sbf[c], ls = sbs[c];
#pragma unroll
        for (int k = 0; k < 38; k++) {
            lf += z[k] * sWf[k * 3 + c];
            ls += z[k] * sWs[k * 3 + c];
        }
        float m = sigmoidf_(lf) * softplusf_(ls);
        atomicAdd(&agg[dst * 3 + c], m);
    }
}

// ---------------- node projection after conv1 ----------------
__global__ void k_node1(const float* __restrict__ x, const float* __restrict__ agg,
                        const float* __restrict__ Wp, const float* __restrict__ bp,
                        float* __restrict__ h, __half* __restrict__ hh) {
    int n = blockIdx.x;
    int c = threadIdx.x;
    __shared__ float sx[3];
    if (c < 3) sx[c] = x[n * 3 + c] + agg[n * 3 + c];
    __syncthreads();
    float v = bp[c] + sx[0] * Wp[c] + sx[1] * Wp[128 + c] + sx[2] * Wp[256 + c];
    v = fmaxf(v, 0.0f);
    h[n * HID + c] = v;
    hh[n * HID + c] = __float2half_rn(v);
}

// ---------------- per-node projections via fp16 mma ----------------
#define PJ_S 136
__global__ __launch_bounds__(256, 3) void k_proj_f16(
        const __half* __restrict__ hh,
        const float* __restrict__ Wf, const float* __restrict__ Ws,
        const float* __restrict__ bf, const float* __restrict__ bs,
        __half* __restrict__ PA, __half* __restrict__ PB) {
    extern __shared__ __half psm[];
    __half* hs  = psm;                 // [128 rows][136]
    __half* wsT = psm + 128 * PJ_S;    // [128 cols][136 k]

    int part = blockIdx.y;
    const float* W; const float* bias; __half* out; int coloff;
    if (part == 0)      { W = Wf;             bias = bf;      out = PA; coloff = 0;   }
    else if (part == 1) { W = Ws;             bias = bs;      out = PA; coloff = 128; }
    else if (part == 2) { W = Wf + 128 * 128; bias = nullptr; out = PB; coloff = 0;   }
    else                { W = Ws + 128 * 128; bias = nullptr; out = PB; coloff = 128; }

    int t = threadIdx.x;
    int lane = t & 31;
    int w = t >> 5;
    int g = lane >> 2;
    int tig = lane & 3;
    int n0 = blockIdx.x * 128;

    // stage h tile (fp16, coalesced)
#pragma unroll
    for (int j = 0; j < 8; j++) {
        int idx = t + j * 256;           // uint4 index (8 halves)
        int row = idx >> 4;
        int c = (idx & 15) * 8;
        uint4 v = make_uint4(0, 0, 0, 0);
        int n = n0 + row;
        if (n < N_NODES) v = *(const uint4*)&hh[(size_t)n * 128 + c];
        *(uint4*)&hs[row * PJ_S + c] = v;
    }
    // stage W transposed fp16: wsT[c][k] = W[k][c]
#pragma unroll
    for (int j = 0; j < 16; j++) {
        int idx4 = t + j * 256;          // float4 index, 4096 total
        int k = idx4 >> 5;
        int c = (idx4 & 31) * 4;
        float4 v = *(const float4*)&W[k * 128 + c];
        wsT[(c + 0) * PJ_S + k] = __float2half_rn(v.x);
        wsT[(c + 1) * PJ_S + k] = __float2half_rn(v.y);
        wsT[(c + 2) * PJ_S + k] = __float2half_rn(v.z);
        wsT[(c + 3) * PJ_S + k] = __float2half_rn(v.w);
    }
    __syncthreads();

    int r0 = w * 16;
#pragma unroll
    for (int h2i = 0; h2i < 2; h2i++) {
        float acc[8][4];
#pragma unroll
        for (int i = 0; i < 8; i++)
#pragma unroll
            for (int j = 0; j < 4; j++) acc[i][j] = 0.0f;
#pragma unroll
        for (int kb8 = 0; kb8 < 8; kb8++) {
            int kb = kb8 * 16;
            unsigned a0 = *(const unsigned*)&hs[(r0 + g) * PJ_S + kb + 2 * tig];
            unsigned a1 = *(const unsigned*)&hs[(r0 + g + 8) * PJ_S + kb + 2 * tig];
            unsigned a2 = *(const unsigned*)&hs[(r0 + g) * PJ_S + kb + 2 * tig + 8];
            unsigned a3 = *(const unsigned*)&hs[(r0 + g + 8) * PJ_S + kb + 2 * tig + 8];
#pragma unroll
            for (int nt = 0; nt < 8; nt++) {
                int col = h2i * 64 + nt * 8 + g;
                unsigned b0 = *(const unsigned*)&wsT[col * PJ_S + kb + 2 * tig];
                unsigned b1 = *(const unsigned*)&wsT[col * PJ_S + kb + 2 * tig + 8];
                mma_f16(acc[nt], a0, a1, a2, a3, b0, b1);
            }
        }
#pragma unroll
        for (int nt = 0; nt < 8; nt++) {
            int c = h2i * 64 + nt * 8 + 2 * tig;
            float b0 = 0.f, b1 = 0.f;
            if (bias) { b0 = bias[c]; b1 = bias[c + 1]; }
            int n = n0 + r0 + g;
            if (n < N_NODES)
                *(half2*)&out[(size_t)n * 256 + coloff + c] =
                    __floats2half2_rn(acc[nt][0] + b0, acc[nt][1] + b1);
            n = n0 + r0 + g + 8;
            if (n < N_NODES)
                *(half2*)&out[(size_t)n * 256 + coloff + c] =
                    __floats2half2_rn(acc[nt][2] + b0, acc[nt][3] + b1);
        }
    }
}

// ---------------- fused edge kernel over CSR-sorted edges ----------------
#define WT_S 40
#define EA_S 40
#define EH_S 264
__global__ __launch_bounds__(256, 3) void k_edge_fused(
        const int* __restrict__ srcs, const int* __restrict__ dsts,
        const __half* __restrict__ eas,
        const __half* __restrict__ PA, const __half* __restrict__ PB,
        const float* __restrict__ Wf, const float* __restrict__ Ws,
        float* __restrict__ agg) {
    extern __shared__ __half sm[];
    __half* wsT  = sm;                          // 256*40  W transposed [col][k]
    __half* seas = sm + 256 * WT_S;             // 64*40   ea tile
    __half* Eh   = sm + 256 * WT_S + 64 * EA_S; // 64*264  E tile

    int t = threadIdx.x;
    int lane = t & 31;
    int w = t >> 5;
    int g = lane >> 2;
    int tig = lane & 3;

    // stage W transposed (rows 256..287): wsT[c][k] = W[256+k][c]
#pragma unroll
    for (int j = 0; j < 32; j++) {
        int idx = t + j * 256;
        int k = idx >> 8;
        int c = idx & 255;
        float v = (c < 128) ? Wf[(256 + k) * 128 + c]
                            : Ws[(256 + k) * 128 + (c - 128)];
        wsT[c * WT_S + k] = __float2half_rn(v);
    }
    __syncthreads();

    int erow0 = (w & 3) * 16;
    int col0 = (w >> 2) * 128;

    for (int tile = blockIdx.x; tile < NTILES; tile += gridDim.x) {
        long e0 = (long)tile * ETILE;
        // stage ea tile (64 x 32 fp16, coalesced from sorted buffer)
        {
            uint4 v = *(const uint4*)&eas[e0 * 32 + t * 8];
            int row = t >> 2;
            int c = (t & 3) * 8;
            *(uint4*)&seas[row * EA_S + c] = v;
        }
        __syncthreads();

        // phase 1: E = ea @ [Wef|Wes], warp tile 16x128 in 2 halves
#pragma unroll
        for (int h2i = 0; h2i < 2; h2i++) {
            float acc[8][4];
#pragma unroll
            for (int i = 0; i < 8; i++)
#pragma unroll
                for (int j = 0; j < 4; j++) acc[i][j] = 0.0f;
#pragma unroll
            for (int ks = 0; ks < 2; ks++) {
                int kb = ks * 16;
                unsigned a0 = *(const unsigned*)&seas[(erow0 + g) * EA_S + kb + 2 * tig];
                unsigned a1 = *(const unsigned*)&seas[(erow0 + g + 8) * EA_S + kb + 2 * tig];
                unsigned a2 = *(const unsigned*)&seas[(erow0 + g) * EA_S + kb + 2 * tig + 8];
                unsigned a3 = *(const unsigned*)&seas[(erow0 + g + 8) * EA_S + kb + 2 * tig + 8];
#pragma unroll
                for (int nt = 0; nt < 8; nt++) {
                    int col = col0 + h2i * 64 + nt * 8 + g;
                    unsigned b0 = *(const unsigned*)&wsT[col * WT_S + kb + 2 * tig];
                    unsigned b1 = *(const unsigned*)&wsT[col * WT_S + kb + 2 * tig + 8];
                    mma_f16(acc[nt], a0, a1, a2, a3, b0, b1);
                }
            }
#pragma unroll
            for (int nt = 0; nt < 8; nt++) {
                int c = col0 + h2i * 64 + nt * 8 + 2 * tig;
                *(half2*)&Eh[(erow0 + g) * EH_S + c]     = __floats2half2_rn(acc[nt][0], acc[nt][1]);
                *(half2*)&Eh[(erow0 + g + 8) * EH_S + c] = __floats2half2_rn(acc[nt][2], acc[nt][3]);
            }
        }
        __syncthreads();

        // phase 2: dst-sorted group accumulation (warp w: edges w*8..w*8+7)
        {
            int prev = -1;
            float4 acc = make_float4(0.f, 0.f, 0.f, 0.f);
            float2 af0, af1, as0, as1;
            af0 = af1 = as0 = as1 = make_float2(0.f, 0.f);
#pragma unroll
            for (int j = 0; j < 8; j++) {
                int le = w * 8 + j;
                long e = e0 + le;
                int dst = dsts[e];
                int src = srcs[e];
                if (dst != prev) {
                    if (prev >= 0)
                        red4(&agg[(size_t)prev * HID + lane * 4], acc);
                    acc = make_float4(0.f, 0.f, 0.f, 0.f);
                    uint2 pafu = *(const uint2*)&PA[(size_t)dst * 256 + lane * 4];
                    uint2 pasu = *(const uint2*)&PA[(size_t)dst * 256 + 128 + lane * 4];
                    af0 = __half22float2(*(half2*)&pafu.x);
                    af1 = __half22float2(*(half2*)&pafu.y);
                    as0 = __half22float2(*(half2*)&pasu.x);
                    as1 = __half22float2(*(half2*)&pasu.y);
                    prev = dst;
                }
                uint2 efu = *(const uint2*)&Eh[le * EH_S + lane * 4];
                uint2 esu = *(const uint2*)&Eh[le * EH_S + 128 + lane * 4];
                uint2 pbfu = *(const uint2*)&PB[(size_t)src * 256 + lane * 4];
                uint2 pbsu = *(const uint2*)&PB[(size_t)src * 256 + 128 + lane * 4];

                float2 ef0 = __half22float2(*(half2*)&efu.x),  ef1 = __half22float2(*(half2*)&efu.y);
                float2 es0 = __half22float2(*(half2*)&esu.x),  es1 = __half22float2(*(half2*)&esu.y);
                float2 bf0 = __half22float2(*(half2*)&pbfu.x), bf1 = __half22float2(*(half2*)&pbfu.y);
                float2 bs0 = __half22float2(*(half2*)&pbsu.x), bs1 = __half22float2(*(half2*)&pbsu.y);

                acc.x += sigmoidf_(ef0.x + af0.x + bf0.x) * softplusf_(es0.x + as0.x + bs0.x);
                acc.y += sigmoidf_(ef0.y + af0.y + bf0.y) * softplusf_(es0.y + as0.y + bs0.y);
                acc.z += sigmoidf_(ef1.x + af1.x + bf1.x) * softplusf_(es1.x + as1.x + bs1.x);
                acc.w += sigmoidf_(ef1.y + af1.y + bf1.y) * softplusf_(es1.y + as1.y + bs1.y);
            }
            if (prev >= 0)
                red4(&agg[(size_t)prev * HID + lane * 4], acc);
        }
        __syncthreads();
    }
}

// ---------------- residual + relu (+ fp16 mirror) ----------------
__global__ void k_update(float* __restrict__ h, __half* __restrict__ hh,
                         const float* __restrict__ agg, int n) {
    int i = blockIdx.x * blockDim.x + threadIdx.x;
    int stride = gridDim.x * blockDim.x;
    for (; i < n; i += stride) {
        float v = fmaxf(h[i] + agg[i], 0.0f);
        h[i] = v;
        hh[i] = __float2half_rn(v);
    }
}

// ---------------- pooling (batch sorted) ----------------
__global__ void k_pool(const float* __restrict__ h, const int* __restrict__ batch,
                       float* __restrict__ pool, float* __restrict__ cnt) {
    const int NPB = 256;
    int n0 = blockIdx.x * NPB;
    if (n0 >= N_NODES) return;
    int c = threadIdx.x;
    float s = 0.0f;
    int cur = batch[n0];
    int mycnt = 0;
    for (int i = 0; i < NPB; i++) {
        int n = n0 + i;
        if (n >= N_NODES) break;
        int b = batch[n];
        if (b != cur) {
            atomicAdd(&pool[cur * HID + c], s);
            if (c == 0) atomicAdd(&cnt[cur], (float)mycnt);
            s = 0.0f; mycnt = 0; cur = b;
        }
        s += h[n * HID + c];
        mycnt++;
    }
    atomicAdd(&pool[cur * HID + c], s);
    if (c == 0) atomicAdd(&cnt[cur], (float)mycnt);
}

// ---------------- head ----------------
__global__ void k_head(const float* __restrict__ pool, const float* __restrict__ cnt,
                       const float* __restrict__ W1, const float* __restrict__ b1,
                       const float* __restrict__ W2, const float* __restrict__ b2,
                       float* __restrict__ out) {
    int g = blockIdx.x;
    int c = threadIdx.x;
    __shared__ float p[128];
    __shared__ float t1[128];
    float invc = 1.0f / fmaxf(cnt[g], 1.0f);
    p[c] = pool[g * HID + c] * invc;
    __syncthreads();
    float v = b1[c];
#pragma unroll 16
    for (int k = 0; k < 128; k++) v += p[k] * W1[k * 128 + c];
    t1[c] = fmaxf(v, 0.0f);
    __syncthreads();
    if (c < 3) {
        float o = b2[c];
        for (int k = 0; k < 128; k++) o += t1[k] * W2[k * 3 + c];
        out[g * 3 + c] = o;
    }
}

// ---------------- launch ----------------
extern "C" void kernel_launch(void* const* d_in, const int* in_sizes, int n_in,
                              void* d_out, int out_size) {
    const float* x   = (const float*)d_in[0];
    const int*   ei  = (const int*)d_in[1];
    const float* ea  = (const float*)d_in[2];
    const int*   bat = (const int*)d_in[3];
    const float* Wf1 = (const float*)d_in[4];
    const float* bf1 = (const float*)d_in[5];
    const float* Ws1 = (const float*)d_in[6];
    const float* bs1 = (const float*)d_in[7];
    const float* Wp  = (const float*)d_in[8];
    const float* bp  = (const float*)d_in[9];
    const float* Wc[2]  = { (const float*)d_in[10], (const float*)d_in[14] };
    const float* bcf[2] = { (const float*)d_in[11], (const float*)d_in[15] };
    const float* Wsc[2] = { (const float*)d_in[12], (const float*)d_in[16] };
    const float* bcs[2] = { (const float*)d_in[13], (const float*)d_in[17] };
    const float* W1  = (const float*)d_in[18];
    const float* b1  = (const float*)d_in[19];
    const float* W2  = (const float*)d_in[20];
    const float* b2  = (const float*)d_in[21];
    float* out = (float*)d_out;

    float *pH, *pAgg, *pPool;
    __half *pPA, *pPB, *pHH, *pEAS;
    int *pDeg, *pCur, *pPart, *pSrcs, *pDsts;
    cudaGetSymbolAddress((void**)&pH,    g_h);
    cudaGetSymbolAddress((void**)&pHH,   g_hh);
    cudaGetSymbolAddress((void**)&pPA,   g_PA);
    cudaGetSymbolAddress((void**)&pPB,   g_PB);
    cudaGetSymbolAddress((void**)&pAgg,  g_agg);
    cudaGetSymbolAddress((void**)&pPool, g_pool);
    cudaGetSymbolAddress((void**)&pDeg,  g_deg);
    cudaGetSymbolAddress((void**)&pCur,  g_cursor);
    cudaGetSymbolAddress((void**)&pPart, g_part);
    cudaGetSymbolAddress((void**)&pSrcs, g_srcs);
    cudaGetSymbolAddress((void**)&pDsts, g_dsts);
    cudaGetSymbolAddress((void**)&pEAS,  g_eas);

    const int EDGE_SMEM = (256 * WT_S + 64 * EA_S + 64 * EH_S) * 2;
    const int PROJ_SMEM = 2 * 128 * PJ_S * 2;
    cudaFuncSetAttribute(k_edge_fused, cudaFuncAttributeMaxDynamicSharedMemorySize, EDGE_SMEM);
    cudaFuncSetAttribute(k_proj_f16, cudaFuncAttributeMaxDynamicSharedMemorySize, PROJ_SMEM);

    // ---- build CSR (sorted by dst) ----
    k_zero_int<<<128, 512>>>(pDeg, N_NODES);
    k_hist<<<N_EDGES / 256, 256>>>(ei, pDeg);
    k_scan_a<<<SCAN_NB, SCAN_B>>>(pDeg, pCur, pPart);
    k_scan_b<<<1, 256>>>(pPart, SCAN_NB);
    k_scan_c<<<SCAN_NB, SCAN_B>>>(pCur, pPart);
    k_csr<<<N_EDGES / 256, 256>>>(ei, ea, pCur, pSrcs, pDsts, pEAS);

    // ---- conv1 ----
    k_zero<<<512, 256>>>(pAgg, N_NODES * 3);
    k_conv1<<<(N_EDGES + 255) / 256, 256>>>(x, ei, ea, Wf1, bf1, Ws1, bs1, pAgg);
    k_node1<<<N_NODES, 128>>>(x, pAgg, Wp, bp, pH, pHH);

    // ---- hidden convs ----
    for (int l = 0; l < 2; l++) {
        dim3 pg((N_NODES + 127) / 128, 4);
        k_proj_f16<<<pg, 256, PROJ_SMEM>>>(pHH, Wc[l], Wsc[l], bcf[l], bcs[l], pPA, pPB);
        k_zero<<<2048, 256>>>(pAgg, N_NODES * HID);
        k_edge_fused<<<444, 256, EDGE_SMEM>>>(pSrcs, pDsts, pEAS, pPA, pPB,
                                              Wc[l], Wsc[l], pAgg);
        k_update<<<2048, 256>>>(pH, pHH, pAgg, N_NODES * HID);
    }

    // ---- pooling + head ----
    k_zero<<<64, 256>>>(pPool, NGRAPH * HID + NGRAPH);
    k_pool<<<(N_NODES + 255) / 256, 128>>>(pH, bat, pPool, pPool + NGRAPH * HID);
    k_head<<<NGRAPH, 128>>>(pPool, pPool + NGRAPH * HID, W1, b1, W2, b2, out);
}

// round 5
// speedup vs baseline: 1.2152x; 1.2152x over previous
#include <cuda_runtime.h>
#include <cuda_fp16.h>
#include <math.h>

#define N_NODES 100000
#define N_EDGES 1600000
#define HID 128
#define NGRAPH 64
#define ETILE 64
#define NTILES (N_EDGES / ETILE)
#define SCAN_B 512
#define SCAN_NB ((N_NODES + SCAN_B - 1) / SCAN_B)   // 196

// ---------------- device scratch ----------------
__device__ float  g_h[N_NODES * HID];
__device__ __half g_hh[N_NODES * HID];     // fp16 mirror of h for mma
__device__ __half g_PA[N_NODES * 256];     // dst-parts [f|s] (+bias)
__device__ __half g_PB[N_NODES * 256];     // src-parts
__device__ float  g_agg[N_NODES * HID];
__device__ float  g_pool[NGRAPH * HID + NGRAPH];
// CSR (sorted-by-dst edge structure)
__device__ int    g_deg[N_NODES];
__device__ int    g_cursor[N_NODES];
__device__ int    g_part[256];
__device__ int    g_srcs[N_EDGES];
__device__ int    g_dsts[N_EDGES];
__device__ __half g_eas[(size_t)N_EDGES * 32];

// ---------------- helpers ----------------
__device__ __forceinline__ float sigmoidf_(float x) { return 1.0f / (1.0f + __expf(-x)); }
__device__ __forceinline__ float softplusf_(float x) {
    return fmaxf(x, 0.0f) + __logf(1.0f + __expf(-fabsf(x)));
}
// NOTE: no "memory" clobber — this kernel never reads agg, and the clobber
// was serializing every subsequent load behind the reduction.
__device__ __forceinline__ void red4(float* p, float4 v) {
    asm volatile("red.global.add.v4.f32 [%0], {%1,%2,%3,%4};"
                 :: "l"(p), "f"(v.x), "f"(v.y), "f"(v.z), "f"(v.w));
}
__device__ __forceinline__ void mma_f16(float d[4],
                                        unsigned a0, unsigned a1, unsigned a2, unsigned a3,
                                        unsigned b0, unsigned b1) {
    asm volatile("mma.sync.aligned.m16n8k16.row.col.f32.f16.f16.f32 "
                 "{%0,%1,%2,%3}, {%4,%5,%6,%7}, {%8,%9}, {%0,%1,%2,%3};\n"
                 : "+f"(d[0]), "+f"(d[1]), "+f"(d[2]), "+f"(d[3])
                 : "r"(a0), "r"(a1), "r"(a2), "r"(a3), "r"(b0), "r"(b1));
}

// ---------------- zero kernels ----------------
__global__ void k_zero(float* __restrict__ p, int n) {
    int i = blockIdx.x * blockDim.x + threadIdx.x;
    int s = gridDim.x * blockDim.x;
    for (; i < n; i += s) p[i] = 0.0f;
}
__global__ void k_zero_int(int* __restrict__ p, int n) {
    int i = blockIdx.x * blockDim.x + threadIdx.x;
    int s = gridDim.x * blockDim.x;
    for (; i < n; i += s) p[i] = 0;
}

// ---------------- CSR build ----------------
__global__ void k_hist(const int* __restrict__ ei, int* __restrict__ deg) {
    int e = blockIdx.x * blockDim.x + threadIdx.x;
    if (e < N_EDGES) atomicAdd(&deg[ei[N_EDGES + e]], 1);
}
__global__ void k_scan_a(const int* __restrict__ deg, int* __restrict__ cursor,
                         int* __restrict__ part) {
    __shared__ int s[SCAN_B];
    int i = blockIdx.x * SCAN_B + threadIdx.x;
    int v = (i < N_NODES) ? deg[i] : 0;
    s[threadIdx.x] = v;
    __syncthreads();
    for (int off = 1; off < SCAN_B; off <<= 1) {
        int t = (threadIdx.x >= off) ? s[threadIdx.x - off] : 0;
        __syncthreads();
        s[threadIdx.x] += t;
        __syncthreads();
    }
    if (i < N_NODES) cursor[i] = s[threadIdx.x] - v;
    if (threadIdx.x == SCAN_B - 1) part[blockIdx.x] = s[threadIdx.x];
}
__global__ void k_scan_b(int* __restrict__ part, int nb) {
    __shared__ int s[256];
    int v = (threadIdx.x < nb) ? part[threadIdx.x] : 0;
    s[threadIdx.x] = v;
    __syncthreads();
    for (int off = 1; off < 256; off <<= 1) {
        int t = (threadIdx.x >= off) ? s[threadIdx.x - off] : 0;
        __syncthreads();
        s[threadIdx.x] += t;
        __syncthreads();
    }
    if (threadIdx.x < nb) part[threadIdx.x] = s[threadIdx.x] - v;
}
__global__ void k_scan_c(int* __restrict__ cursor, const int* __restrict__ part) {
    int i = blockIdx.x * SCAN_B + threadIdx.x;
    if (i < N_NODES) cursor[i] += part[blockIdx.x];
}

// ---------------- fused CSR scatter + conv1 (single ea pass) ----------------
__global__ void k_csr_conv1(const float* __restrict__ x, const int* __restrict__ ei,
                            const float* __restrict__ ea,
                            const float* __restrict__ Wf, const float* __restrict__ bf,
                            const float* __restrict__ Ws, const float* __restrict__ bs,
                            int* __restrict__ cursor,
                            int* __restrict__ srcs, int* __restrict__ dsts,
                            __half* __restrict__ eas, float* __restrict__ agg) {
    __shared__ float sWf[38 * 3], sWs[38 * 3], sbf[3], sbs[3];
    int t = threadIdx.x;
    if (t < 114) { sWf[t] = Wf[t]; sWs[t] = Ws[t]; }
    if (t < 3)   { sbf[t] = bf[t]; sbs[t] = bs[t]; }
    __syncthreads();
    int e = blockIdx.x * blockDim.x + t;
    if (e >= N_EDGES) return;
    int src = ei[e];
    int dst = ei[N_EDGES + e];

    float z[38];
    z[0] = x[dst * 3 + 0]; z[1] = x[dst * 3 + 1]; z[2] = x[dst * 3 + 2];
    z[3] = x[src * 3 + 0]; z[4] = x[src * 3 + 1]; z[5] = x[src * 3 + 2];
    float4 v[8];
    const float4* s = (const float4*)&ea[(size_t)e * 32];
#pragma unroll
    for (int j = 0; j < 8; j++) {
        v[j] = s[j];
        z[6 + j * 4 + 0] = v[j].x; z[6 + j * 4 + 1] = v[j].y;
        z[6 + j * 4 + 2] = v[j].z; z[6 + j * 4 + 3] = v[j].w;
    }
    // conv1 message (3 channels)
#pragma unroll
    for (int c = 0; c < 3; c++) {
        float lf = sbf[c], ls = sbs[c];
#pragma unroll
        for (int k = 0; k < 38; k++) {
            lf += z[k] * sWf[k * 3 + c];
            ls += z[k] * sWs[k * 3 + c];
        }
        float m = sigmoidf_(lf) * softplusf_(ls);
        atomicAdd(&agg[dst * 3 + c], m);
    }
    // CSR scatter + fp16 conversion
    int pos = atomicAdd(&cursor[dst], 1);
    srcs[pos] = src;
    dsts[pos] = dst;
    __half* d = &eas[(size_t)pos * 32];
#pragma unroll
    for (int j = 0; j < 8; j++) {
        *(half2*)&d[j * 4]     = __floats2half2_rn(v[j].x, v[j].y);
        *(half2*)&d[j * 4 + 2] = __floats2half2_rn(v[j].z, v[j].w);
    }
}

// ---------------- node projection after conv1 ----------------
__global__ void k_node1(const float* __restrict__ x, const float* __restrict__ agg,
                        const float* __restrict__ Wp, const float* __restrict__ bp,
                        float* __restrict__ h, __half* __restrict__ hh) {
    int n = blockIdx.x;
    int c = threadIdx.x;
    __shared__ float sx[3];
    if (c < 3) sx[c] = x[n * 3 + c] + agg[n * 3 + c];
    __syncthreads();
    float v = bp[c] + sx[0] * Wp[c] + sx[1] * Wp[128 + c] + sx[2] * Wp[256 + c];
    v = fmaxf(v, 0.0f);
    h[n * HID + c] = v;
    hh[n * HID + c] = __float2half_rn(v);
}

// ---------------- per-node projections via fp16 mma ----------------
#define PJ_S 136
__global__ __launch_bounds__(256, 3) void k_proj_f16(
        const __half* __restrict__ hh,
        const float* __restrict__ Wf, const float* __restrict__ Ws,
        const float* __restrict__ bf, const float* __restrict__ bs,
        __half* __restrict__ PA, __half* __restrict__ PB) {
    extern __shared__ __half psm[];
    __half* hs  = psm;                 // [128 rows][136]
    __half* wsT = psm + 128 * PJ_S;    // [128 cols][136 k]

    int part = blockIdx.y;
    const float* W; const float* bias; __half* out; int coloff;
    if (part == 0)      { W = Wf;             bias = bf;      out = PA; coloff = 0;   }
    else if (part == 1) { W = Ws;             bias = bs;      out = PA; coloff = 128; }
    else if (part == 2) { W = Wf + 128 * 128; bias = nullptr; out = PB; coloff = 0;   }
    else                { W = Ws + 128 * 128; bias = nullptr; out = PB; coloff = 128; }

    int t = threadIdx.x;
    int lane = t & 31;
    int w = t >> 5;
    int g = lane >> 2;
    int tig = lane & 3;
    int n0 = blockIdx.x * 128;

#pragma unroll
    for (int j = 0; j < 8; j++) {
        int idx = t + j * 256;
        int row = idx >> 4;
        int c = (idx & 15) * 8;
        uint4 v = make_uint4(0, 0, 0, 0);
        int n = n0 + row;
        if (n < N_NODES) v = *(const uint4*)&hh[(size_t)n * 128 + c];
        *(uint4*)&hs[row * PJ_S + c] = v;
    }
#pragma unroll
    for (int j = 0; j < 16; j++) {
        int idx4 = t + j * 256;
        int k = idx4 >> 5;
        int c = (idx4 & 31) * 4;
        float4 v = *(const float4*)&W[k * 128 + c];
        wsT[(c + 0) * PJ_S + k] = __float2half_rn(v.x);
        wsT[(c + 1) * PJ_S + k] = __float2half_rn(v.y);
        wsT[(c + 2) * PJ_S + k] = __float2half_rn(v.z);
        wsT[(c + 3) * PJ_S + k] = __float2half_rn(v.w);
    }
    __syncthreads();

    int r0 = w * 16;
#pragma unroll
    for (int h2i = 0; h2i < 2; h2i++) {
        float acc[8][4];
#pragma unroll
        for (int i = 0; i < 8; i++)
#pragma unroll
            for (int j = 0; j < 4; j++) acc[i][j] = 0.0f;
#pragma unroll
        for (int kb8 = 0; kb8 < 8; kb8++) {
            int kb = kb8 * 16;
            unsigned a0 = *(const unsigned*)&hs[(r0 + g) * PJ_S + kb + 2 * tig];
            unsigned a1 = *(const unsigned*)&hs[(r0 + g + 8) * PJ_S + kb + 2 * tig];
            unsigned a2 = *(const unsigned*)&hs[(r0 + g) * PJ_S + kb + 2 * tig + 8];
            unsigned a3 = *(const unsigned*)&hs[(r0 + g + 8) * PJ_S + kb + 2 * tig + 8];
#pragma unroll
            for (int nt = 0; nt < 8; nt++) {
                int col = h2i * 64 + nt * 8 + g;
                unsigned b0 = *(const unsigned*)&wsT[col * PJ_S + kb + 2 * tig];
                unsigned b1 = *(const unsigned*)&wsT[col * PJ_S + kb + 2 * tig + 8];
                mma_f16(acc[nt], a0, a1, a2, a3, b0, b1);
            }
        }
#pragma unroll
        for (int nt = 0; nt < 8; nt++) {
            int c = h2i * 64 + nt * 8 + 2 * tig;
            float b0 = 0.f, b1 = 0.f;
            if (bias) { b0 = bias[c]; b1 = bias[c + 1]; }
            int n = n0 + r0 + g;
            if (n < N_NODES)
                *(half2*)&out[(size_t)n * 256 + coloff + c] =
                    __floats2half2_rn(acc[nt][0] + b0, acc[nt][1] + b1);
            n = n0 + r0 + g + 8;
            if (n < N_NODES)
                *(half2*)&out[(size_t)n * 256 + coloff + c] =
                    __floats2half2_rn(acc[nt][2] + b0, acc[nt][3] + b1);
        }
    }
}

// ---------------- fused edge kernel over CSR-sorted edges ----------------
#define WT_S 40
#define EA_S 40
#define EH_S 264
__global__ __launch_bounds__(256, 3) void k_edge_fused(
        const int* __restrict__ srcs, const int* __restrict__ dsts,
        const __half* __restrict__ eas,
        const __half* __restrict__ PA, const __half* __restrict__ PB,
        const float* __restrict__ Wf, const float* __restrict__ Ws,
        float* __restrict__ agg) {
    extern __shared__ __half sm[];
    __half* wsT  = sm;                          // 256*40
    __half* seas = sm + 256 * WT_S;             // 64*40
    __half* Eh   = sm + 256 * WT_S + 64 * EA_S; // 64*264

    int t = threadIdx.x;
    int lane = t & 31;
    int w = t >> 5;
    int g = lane >> 2;
    int tig = lane & 3;

#pragma unroll
    for (int j = 0; j < 32; j++) {
        int idx = t + j * 256;
        int k = idx >> 8;
        int c = idx & 255;
        float v = (c < 128) ? Wf[(256 + k) * 128 + c]
                            : Ws[(256 + k) * 128 + (c - 128)];
        wsT[c * WT_S + k] = __float2half_rn(v);
    }
    __syncthreads();

    int erow0 = (w & 3) * 16;
    int col0 = (w >> 2) * 128;

    for (int tile = blockIdx.x; tile < NTILES; tile += gridDim.x) {
        long e0 = (long)tile * ETILE;
        {
            uint4 v = *(const uint4*)&eas[e0 * 32 + t * 8];
            int row = t >> 2;
            int c = (t & 3) * 8;
            *(uint4*)&seas[row * EA_S + c] = v;
        }
        __syncthreads();

        // phase 1: E = ea @ [Wef|Wes], warp tile 16x128 in 2 halves
#pragma unroll
        for (int h2i = 0; h2i < 2; h2i++) {
            float acc[8][4];
#pragma unroll
            for (int i = 0; i < 8; i++)
#pragma unroll
                for (int j = 0; j < 4; j++) acc[i][j] = 0.0f;
#pragma unroll
            for (int ks = 0; ks < 2; ks++) {
                int kb = ks * 16;
                unsigned a0 = *(const unsigned*)&seas[(erow0 + g) * EA_S + kb + 2 * tig];
                unsigned a1 = *(const unsigned*)&seas[(erow0 + g + 8) * EA_S + kb + 2 * tig];
                unsigned a2 = *(const unsigned*)&seas[(erow0 + g) * EA_S + kb + 2 * tig + 8];
                unsigned a3 = *(const unsigned*)&seas[(erow0 + g + 8) * EA_S + kb + 2 * tig + 8];
#pragma unroll
                for (int nt = 0; nt < 8; nt++) {
                    int col = col0 + h2i * 64 + nt * 8 + g;
                    unsigned b0 = *(const unsigned*)&wsT[col * WT_S + kb + 2 * tig];
                    unsigned b1 = *(const unsigned*)&wsT[col * WT_S + kb + 2 * tig + 8];
                    mma_f16(acc[nt], a0, a1, a2, a3, b0, b1);
                }
            }
#pragma unroll
            for (int nt = 0; nt < 8; nt++) {
                int c = col0 + h2i * 64 + nt * 8 + 2 * tig;
                *(half2*)&Eh[(erow0 + g) * EH_S + c]     = __floats2half2_rn(acc[nt][0], acc[nt][1]);
                *(half2*)&Eh[(erow0 + g + 8) * EH_S + c] = __floats2half2_rn(acc[nt][2], acc[nt][3]);
            }
        }
        __syncthreads();

        // phase 2: batched-prefetch gather + grouped flush
        {
            int srcs8[8], dsts8[8];
#pragma unroll
            for (int j = 0; j < 8; j++) {
                long e = e0 + w * 8 + j;
                srcs8[j] = srcs[e];
                dsts8[j] = dsts[e];
            }
            int prev = -1;
            float4 acc = make_float4(0.f, 0.f, 0.f, 0.f);
            float2 af0, af1, as0, as1;
            af0 = af1 = as0 = as1 = make_float2(0.f, 0.f);
#pragma unroll
            for (int b = 0; b < 2; b++) {
                // prefetch PB for 4 edges (independent loads, no barrier between)
                uint2 pbf[4], pbs[4];
#pragma unroll
                for (int j = 0; j < 4; j++) {
                    size_t base = (size_t)srcs8[b * 4 + j] * 256 + lane * 4;
                    pbf[j] = *(const uint2*)&PB[base];
                    pbs[j] = *(const uint2*)&PB[base + 128];
                }
#pragma unroll
                for (int j = 0; j < 4; j++) {
                    int le = w * 8 + b * 4 + j;
                    int dst = dsts8[b * 4 + j];
                    if (dst != prev) {
                        if (prev >= 0)
                            red4(&agg[(size_t)prev * HID + lane * 4], acc);
                        acc = make_float4(0.f, 0.f, 0.f, 0.f);
                        size_t base = (size_t)dst * 256 + lane * 4;
                        uint2 pafu = *(const uint2*)&PA[base];
                        uint2 pasu = *(const uint2*)&PA[base + 128];
                        af0 = __half22float2(*(half2*)&pafu.x);
                        af1 = __half22float2(*(half2*)&pafu.y);
                        as0 = __half22float2(*(half2*)&pasu.x);
                        as1 = __half22float2(*(half2*)&pasu.y);
                        prev = dst;
                    }
                    uint2 efu = *(const uint2*)&Eh[le * EH_S + lane * 4];
                    uint2 esu = *(const uint2*)&Eh[le * EH_S + 128 + lane * 4];

                    float2 ef0 = __half22float2(*(half2*)&efu.x),  ef1 = __half22float2(*(half2*)&efu.y);
                    float2 es0 = __half22float2(*(half2*)&esu.x),  es1 = __half22float2(*(half2*)&esu.y);
                    float2 bf0 = __half22float2(*(half2*)&pbf[j].x), bf1 = __half22float2(*(half2*)&pbf[j].y);
                    float2 bs0 = __half22float2(*(half2*)&pbs[j].x), bs1 = __half22float2(*(half2*)&pbs[j].y);

                    acc.x += sigmoidf_(ef0.x + af0.x + bf0.x) * softplusf_(es0.x + as0.x + bs0.x);
                    acc.y += sigmoidf_(ef0.y + af0.y + bf0.y) * softplusf_(es0.y + as0.y + bs0.y);
                    acc.z += sigmoidf_(ef1.x + af1.x + bf1.x) * softplusf_(es1.x + as1.x + bs1.x);
                    acc.w += sigmoidf_(ef1.y + af1.y + bf1.y) * softplusf_(es1.y + as1.y + bs1.y);
                }
            }
            if (prev >= 0)
                red4(&agg[(size_t)prev * HID + lane * 4], acc);
        }
        __syncthreads();
    }
}

// ---------------- residual + relu (+ fp16 mirror) ----------------
__global__ void k_update(float* __restrict__ h, __half* __restrict__ hh,
                         const float* __restrict__ agg, int n) {
    int i = blockIdx.x * blockDim.x + threadIdx.x;
    int stride = gridDim.x * blockDim.x;
    for (; i < n; i += stride) {
        float v = fmaxf(h[i] + agg[i], 0.0f);
        h[i] = v;
        hh[i] = __float2half_rn(v);
    }
}

// ---------------- pooling (batch sorted) ----------------
__global__ void k_pool(const float* __restrict__ h, const int* __restrict__ batch,
                       float* __restrict__ pool, float* __restrict__ cnt) {
    const int NPB = 256;
    int n0 = blockIdx.x * NPB;
    if (n0 >= N_NODES) return;
    int c = threadIdx.x;
    float s = 0.0f;
    int cur = batch[n0];
    int mycnt = 0;
    for (int i = 0; i < NPB; i++) {
        int n = n0 + i;
        if (n >= N_NODES) break;
        int b = batch[n];
        if (b != cur) {
            atomicAdd(&pool[cur * HID + c], s);
            if (c == 0) atomicAdd(&cnt[cur], (float)mycnt);
            s = 0.0f; mycnt = 0; cur = b;
        }
        s += h[n * HID + c];
        mycnt++;
    }
    atomicAdd(&pool[cur * HID + c], s);
    if (c == 0) atomicAdd(&cnt[cur], (float)mycnt);
}

// ---------------- head ----------------
__global__ void k_head(const float* __restrict__ pool, const float* __restrict__ cnt,
                       const float* __restrict__ W1, const float* __restrict__ b1,
                       const float* __restrict__ W2, const float* __restrict__ b2,
                       float* __restrict__ out) {
    int g = blockIdx.x;
    int c = threadIdx.x;
    __shared__ float p[128];
    __shared__ float t1[128];
    float invc = 1.0f / fmaxf(cnt[g], 1.0f);
    p[c] = pool[g * HID + c] * invc;
    __syncthreads();
    float v = b1[c];
#pragma unroll 16
    for (int k = 0; k < 128; k++) v += p[k] * W1[k * 128 + c];
    t1[c] = fmaxf(v, 0.0f);
    __syncthreads();
    if (c < 3) {
        float o = b2[c];
        for (int k = 0; k < 128; k++) o += t1[k] * W2[k * 3 + c];
        out[g * 3 + c] = o;
    }
}

// ---------------- launch ----------------
extern "C" void kernel_launch(void* const* d_in, const int* in_sizes, int n_in,
                              void* d_out, int out_size) {
    const float* x   = (const float*)d_in[0];
    const int*   ei  = (const int*)d_in[1];
    const float* ea  = (const float*)d_in[2];
    const int*   bat = (const int*)d_in[3];
    const float* Wf1 = (const float*)d_in[4];
    const float* bf1 = (const float*)d_in[5];
    const float* Ws1 = (const float*)d_in[6];
    const float* bs1 = (const float*)d_in[7];
    const float* Wp  = (const float*)d_in[8];
    const float* bp  = (const float*)d_in[9];
    const float* Wc[2]  = { (const float*)d_in[10], (const float*)d_in[14] };
    const float* bcf[2] = { (const float*)d_in[11], (const float*)d_in[15] };
    const float* Wsc[2] = { (const float*)d_in[12], (const float*)d_in[16] };
    const float* bcs[2] = { (const float*)d_in[13], (const float*)d_in[17] };
    const float* W1  = (const float*)d_in[18];
    const float* b1  = (const float*)d_in[19];
    const float* W2  = (const float*)d_in[20];
    const float* b2  = (const float*)d_in[21];
    float* out = (float*)d_out;

    float *pH, *pAgg, *pPool;
    __half *pPA, *pPB, *pHH, *pEAS;
    int *pDeg, *pCur, *pPart, *pSrcs, *pDsts;
    cudaGetSymbolAddress((void**)&pH,    g_h);
    cudaGetSymbolAddress((void**)&pHH,   g_hh);
    cudaGetSymbolAddress((void**)&pPA,   g_PA);
    cudaGetSymbolAddress((void**)&pPB,   g_PB);
    cudaGetSymbolAddress((void**)&pAgg,  g_agg);
    cudaGetSymbolAddress((void**)&pPool, g_pool);
    cudaGetSymbolAddress((void**)&pDeg,  g_deg);
    cudaGetSymbolAddress((void**)&pCur,  g_cursor);
    cudaGetSymbolAddress((void**)&pPart, g_part);
    cudaGetSymbolAddress((void**)&pSrcs, g_srcs);
    cudaGetSymbolAddress((void**)&pDsts, g_dsts);
    cudaGetSymbolAddress((void**)&pEAS,  g_eas);

    const int EDGE_SMEM = (256 * WT_S + 64 * EA_S + 64 * EH_S) * 2;
    const int PROJ_SMEM = 2 * 128 * PJ_S * 2;
    cudaFuncSetAttribute(k_edge_fused, cudaFuncAttributeMaxDynamicSharedMemorySize, EDGE_SMEM);
    cudaFuncSetAttribute(k_proj_f16, cudaFuncAttributeMaxDynamicSharedMemorySize, PROJ_SMEM);

    // ---- build CSR + conv1 in one ea pass ----
    k_zero_int<<<128, 512>>>(pDeg, N_NODES);
    k_hist<<<N_EDGES / 256, 256>>>(ei, pDeg);
    k_scan_a<<<SCAN_NB, SCAN_B>>>(pDeg, pCur, pPart);
    k_scan_b<<<1, 256>>>(pPart, SCAN_NB);
    k_scan_c<<<SCAN_NB, SCAN_B>>>(pCur, pPart);
    k_zero<<<512, 256>>>(pAgg, N_NODES * 3);
    k_csr_conv1<<<N_EDGES / 256, 256>>>(x, ei, ea, Wf1, bf1, Ws1, bs1,
                                        pCur, pSrcs, pDsts, pEAS, pAgg);
    k_node1<<<N_NODES, 128>>>(x, pAgg, Wp, bp, pH, pHH);

    // ---- hidden convs ----
    for (int l = 0; l < 2; l++) {
        dim3 pg((N_NODES + 127) / 128, 4);
        k_proj_f16<<<pg, 256, PROJ_SMEM>>>(pHH, Wc[l], Wsc[l], bcf[l], bcs[l], pPA, pPB);
        k_zero<<<2048, 256>>>(pAgg, N_NODES * HID);
        k_edge_fused<<<444, 256, EDGE_SMEM>>>(pSrcs, pDsts, pEAS, pPA, pPB,
                                              Wc[l], Wsc[l], pAgg);
        k_update<<<2048, 256>>>(pH, pHH, pAgg, N_NODES * HID);
    }

    // ---- pooling + head ----
    k_zero<<<64, 256>>>(pPool, NGRAPH * HID + NGRAPH);
    k_pool<<<(N_NODES + 255) / 256, 128>>>(pH, bat, pPool, pPool + NGRAPH * HID);
    k_head<<<NGRAPH, 128>>>(pPool, pPool + NGRAPH * HID, W1, b1, W2, b2, out);
}

// round 6
// speedup vs baseline: 1.2253x; 1.0083x over previous
#include <cuda_runtime.h>
#include <cuda_fp16.h>
#include <math.h>

#define N_NODES 100000
#define N_EDGES 1600000
#define HID 128
#define NGRAPH 64
#define ETILE 64
#define NTILES (N_EDGES / ETILE)
#define SCAN_B 512
#define SCAN_NB ((N_NODES + SCAN_B - 1) / SCAN_B)   // 196

// ---------------- device scratch ----------------
__device__ float  g_h[N_NODES * HID];
__device__ __half g_hh[N_NODES * HID];
__device__ __half g_PA[N_NODES * 256];
__device__ __half g_PB[N_NODES * 256];
__device__ float  g_agg[N_NODES * HID];
__device__ float  g_pool[NGRAPH * HID + NGRAPH];
__device__ int    g_deg[N_NODES];
__device__ int    g_cursor[N_NODES];
__device__ int    g_part[256];
__device__ int    g_srcs[N_EDGES];
__device__ int    g_dsts[N_EDGES];
__device__ __half g_eas[(size_t)N_EDGES * 32];

// ---------------- helpers ----------------
__device__ __forceinline__ float sigmoidf_(float x) { return 1.0f / (1.0f + __expf(-x)); }
__device__ __forceinline__ float softplusf_(float x) {
    return fmaxf(x, 0.0f) + __logf(1.0f + __expf(-fabsf(x)));
}
__device__ __forceinline__ void red4(float* p, float4 v) {
    asm volatile("red.global.add.v4.f32 [%0], {%1,%2,%3,%4};"
                 :: "l"(p), "f"(v.x), "f"(v.y), "f"(v.z), "f"(v.w));
}
__device__ __forceinline__ void mma_f16(float d[4],
                                        unsigned a0, unsigned a1, unsigned a2, unsigned a3,
                                        unsigned b0, unsigned b1) {
    asm volatile("mma.sync.aligned.m16n8k16.row.col.f32.f16.f16.f32 "
                 "{%0,%1,%2,%3}, {%4,%5,%6,%7}, {%8,%9}, {%0,%1,%2,%3};\n"
                 : "+f"(d[0]), "+f"(d[1]), "+f"(d[2]), "+f"(d[3])
                 : "r"(a0), "r"(a1), "r"(a2), "r"(a3), "r"(b0), "r"(b1));
}

// ---------------- zero kernels ----------------
__global__ void k_zero(float* __restrict__ p, int n) {
    int i = blockIdx.x * blockDim.x + threadIdx.x;
    int s = gridDim.x * blockDim.x;
    for (; i < n; i += s) p[i] = 0.0f;
}
__global__ void k_zero_int(int* __restrict__ p, int n) {
    int i = blockIdx.x * blockDim.x + threadIdx.x;
    int s = gridDim.x * blockDim.x;
    for (; i < n; i += s) p[i] = 0;
}

// ---------------- CSR build ----------------
__global__ void k_hist(const int* __restrict__ ei, int* __restrict__ deg) {
    int e = blockIdx.x * blockDim.x + threadIdx.x;
    if (e < N_EDGES) atomicAdd(&deg[ei[N_EDGES + e]], 1);
}
__global__ void k_scan_a(const int* __restrict__ deg, int* __restrict__ cursor,
                         int* __restrict__ part) {
    __shared__ int s[SCAN_B];
    int i = blockIdx.x * SCAN_B + threadIdx.x;
    int v = (i < N_NODES) ? deg[i] : 0;
    s[threadIdx.x] = v;
    __syncthreads();
    for (int off = 1; off < SCAN_B; off <<= 1) {
        int t = (threadIdx.x >= off) ? s[threadIdx.x - off] : 0;
        __syncthreads();
        s[threadIdx.x] += t;
        __syncthreads();
    }
    if (i < N_NODES) cursor[i] = s[threadIdx.x] - v;
    if (threadIdx.x == SCAN_B - 1) part[blockIdx.x] = s[threadIdx.x];
}
__global__ void k_scan_b(int* __restrict__ part, int nb) {
    __shared__ int s[256];
    int v = (threadIdx.x < nb) ? part[threadIdx.x] : 0;
    s[threadIdx.x] = v;
    __syncthreads();
    for (int off = 1; off < 256; off <<= 1) {
        int t = (threadIdx.x >= off) ? s[threadIdx.x - off] : 0;
        __syncthreads();
        s[threadIdx.x] += t;
        __syncthreads();
    }
    if (threadIdx.x < nb) part[threadIdx.x] = s[threadIdx.x] - v;
}
__global__ void k_scan_c(int* __restrict__ cursor, const int* __restrict__ part) {
    int i = blockIdx.x * SCAN_B + threadIdx.x;
    if (i < N_NODES) cursor[i] += part[blockIdx.x];
}

// ---------------- fused CSR scatter + conv1 (single ea pass) ----------------
__global__ void k_csr_conv1(const float* __restrict__ x, const int* __restrict__ ei,
                            const float* __restrict__ ea,
                            const float* __restrict__ Wf, const float* __restrict__ bf,
                            const float* __restrict__ Ws, const float* __restrict__ bs,
                            int* __restrict__ cursor,
                            int* __restrict__ srcs, int* __restrict__ dsts,
                            __half* __restrict__ eas, float* __restrict__ agg) {
    __shared__ float sWf[38 * 3], sWs[38 * 3], sbf[3], sbs[3];
    int t = threadIdx.x;
    if (t < 114) { sWf[t] = Wf[t]; sWs[t] = Ws[t]; }
    if (t < 3)   { sbf[t] = bf[t]; sbs[t] = bs[t]; }
    __syncthreads();
    int e = blockIdx.x * blockDim.x + t;
    if (e >= N_EDGES) return;
    int src = ei[e];
    int dst = ei[N_EDGES + e];

    float z[38];
    z[0] = x[dst * 3 + 0]; z[1] = x[dst * 3 + 1]; z[2] = x[dst * 3 + 2];
    z[3] = x[src * 3 + 0]; z[4] = x[src * 3 + 1]; z[5] = x[src * 3 + 2];
    float4 v[8];
    const float4* s = (const float4*)&ea[(size_t)e * 32];
#pragma unroll
    for (int j = 0; j < 8; j++) {
        v[j] = s[j];
        z[6 + j * 4 + 0] = v[j].x; z[6 + j * 4 + 1] = v[j].y;
        z[6 + j * 4 + 2] = v[j].z; z[6 + j * 4 + 3] = v[j].w;
    }
#pragma unroll
    for (int c = 0; c < 3; c++) {
        float lf = sbf[c], ls = sbs[c];
#pragma unroll
        for (int k = 0; k < 38; k++) {
            lf += z[k] * sWf[k * 3 + c];
            ls += z[k] * sWs[k * 3 + c];
        }
        float m = sigmoidf_(lf) * softplusf_(ls);
        atomicAdd(&agg[dst * 3 + c], m);
    }
    int pos = atomicAdd(&cursor[dst], 1);
    srcs[pos] = src;
    dsts[pos] = dst;
    __half* d = &eas[(size_t)pos * 32];
#pragma unroll
    for (int j = 0; j < 8; j++) {
        *(half2*)&d[j * 4]     = __floats2half2_rn(v[j].x, v[j].y);
        *(half2*)&d[j * 4 + 2] = __floats2half2_rn(v[j].z, v[j].w);
    }
}

// ---------------- node projection after conv1 ----------------
__global__ void k_node1(const float* __restrict__ x, const float* __restrict__ agg,
                        const float* __restrict__ Wp, const float* __restrict__ bp,
                        float* __restrict__ h, __half* __restrict__ hh) {
    int n = blockIdx.x;
    int c = threadIdx.x;
    __shared__ float sx[3];
    if (c < 3) sx[c] = x[n * 3 + c] + agg[n * 3 + c];
    __syncthreads();
    float v = bp[c] + sx[0] * Wp[c] + sx[1] * Wp[128 + c] + sx[2] * Wp[256 + c];
    v = fmaxf(v, 0.0f);
    h[n * HID + c] = v;
    hh[n * HID + c] = __float2half_rn(v);
}

// ---------------- fused 4-part node projection (stage h ONCE) ----------------
#define PJ_S 136
__global__ __launch_bounds__(256, 3) void k_proj_all(
        const __half* __restrict__ hh,
        const float* __restrict__ Wf, const float* __restrict__ Ws,
        const float* __restrict__ bf, const float* __restrict__ bs,
        __half* __restrict__ PA, __half* __restrict__ PB) {
    extern __shared__ __half psm[];
    __half* hs  = psm;                 // [128 rows][136]
    __half* wsT = psm + 128 * PJ_S;    // [128 cols][136 k]

    int t = threadIdx.x;
    int lane = t & 31;
    int w = t >> 5;
    int g = lane >> 2;
    int tig = lane & 3;
    int n0 = blockIdx.x * 128;

    // stage h tile once
#pragma unroll
    for (int j = 0; j < 8; j++) {
        int idx = t + j * 256;
        int row = idx >> 4;
        int c = (idx & 15) * 8;
        uint4 v = make_uint4(0, 0, 0, 0);
        int n = n0 + row;
        if (n < N_NODES) v = *(const uint4*)&hh[(size_t)n * 128 + c];
        *(uint4*)&hs[row * PJ_S + c] = v;
    }

    int r0 = w * 16;
#pragma unroll 1
    for (int part = 0; part < 4; part++) {
        const float* W; const float* bias; __half* out; int coloff;
        if (part == 0)      { W = Wf;             bias = bf;      out = PA; coloff = 0;   }
        else if (part == 1) { W = Ws;             bias = bs;      out = PA; coloff = 128; }
        else if (part == 2) { W = Wf + 128 * 128; bias = nullptr; out = PB; coloff = 0;   }
        else                { W = Ws + 128 * 128; bias = nullptr; out = PB; coloff = 128; }

        __syncthreads();  // protect wsT re-staging (also orders hs on iter 0)
#pragma unroll
        for (int j = 0; j < 16; j++) {
            int idx4 = t + j * 256;
            int k = idx4 >> 5;
            int c = (idx4 & 31) * 4;
            float4 v = *(const float4*)&W[k * 128 + c];
            wsT[(c + 0) * PJ_S + k] = __float2half_rn(v.x);
            wsT[(c + 1) * PJ_S + k] = __float2half_rn(v.y);
            wsT[(c + 2) * PJ_S + k] = __float2half_rn(v.z);
            wsT[(c + 3) * PJ_S + k] = __float2half_rn(v.w);
        }
        __syncthreads();

#pragma unroll
        for (int h2i = 0; h2i < 2; h2i++) {
            float acc[8][4];
#pragma unroll
            for (int i = 0; i < 8; i++)
#pragma unroll
                for (int j = 0; j < 4; j++) acc[i][j] = 0.0f;
#pragma unroll
            for (int kb8 = 0; kb8 < 8; kb8++) {
                int kb = kb8 * 16;
                unsigned a0 = *(const unsigned*)&hs[(r0 + g) * PJ_S + kb + 2 * tig];
                unsigned a1 = *(const unsigned*)&hs[(r0 + g + 8) * PJ_S + kb + 2 * tig];
                unsigned a2 = *(const unsigned*)&hs[(r0 + g) * PJ_S + kb + 2 * tig + 8];
                unsigned a3 = *(const unsigned*)&hs[(r0 + g + 8) * PJ_S + kb + 2 * tig + 8];
#pragma unroll
                for (int nt = 0; nt < 8; nt++) {
                    int col = h2i * 64 + nt * 8 + g;
                    unsigned b0 = *(const unsigned*)&wsT[col * PJ_S + kb + 2 * tig];
                    unsigned b1 = *(const unsigned*)&wsT[col * PJ_S + kb + 2 * tig + 8];
                    mma_f16(acc[nt], a0, a1, a2, a3, b0, b1);
                }
            }
#pragma unroll
            for (int nt = 0; nt < 8; nt++) {
                int c = h2i * 64 + nt * 8 + 2 * tig;
                float b0 = 0.f, b1 = 0.f;
                if (bias) { b0 = bias[c]; b1 = bias[c + 1]; }
                int n = n0 + r0 + g;
                if (n < N_NODES)
                    *(half2*)&out[(size_t)n * 256 + coloff + c] =
                        __floats2half2_rn(acc[nt][0] + b0, acc[nt][1] + b1);
                n = n0 + r0 + g + 8;
                if (n < N_NODES)
                    *(half2*)&out[(size_t)n * 256 + coloff + c] =
                        __floats2half2_rn(acc[nt][2] + b0, acc[nt][3] + b1);
            }
        }
    }
}

// ---------------- fused edge kernel over CSR-sorted edges ----------------
#define WT_S 40
#define EA_S 40
#define EH_S 264
__global__ __launch_bounds__(256, 3) void k_edge_fused(
        const int* __restrict__ srcs, const int* __restrict__ dsts,
        const __half* __restrict__ eas,
        const __half* __restrict__ PA, const __half* __restrict__ PB,
        const float* __restrict__ Wf, const float* __restrict__ Ws,
        float* __restrict__ agg) {
    extern __shared__ __half sm[];
    __half* wsT  = sm;
    __half* seas = sm + 256 * WT_S;
    __half* Eh   = sm + 256 * WT_S + 64 * EA_S;

    int t = threadIdx.x;
    int lane = t & 31;
    int w = t >> 5;
    int g = lane >> 2;
    int tig = lane & 3;

#pragma unroll
    for (int j = 0; j < 32; j++) {
        int idx = t + j * 256;
        int k = idx >> 8;
        int c = idx & 255;
        float v = (c < 128) ? Wf[(256 + k) * 128 + c]
                            : Ws[(256 + k) * 128 + (c - 128)];
        wsT[c * WT_S + k] = __float2half_rn(v);
    }
    __syncthreads();

    int erow0 = (w & 3) * 16;
    int col0 = (w >> 2) * 128;

    for (int tile = blockIdx.x; tile < NTILES; tile += gridDim.x) {
        long e0 = (long)tile * ETILE;
        {
            uint4 v = *(const uint4*)&eas[e0 * 32 + t * 8];
            int row = t >> 2;
            int c = (t & 3) * 8;
            *(uint4*)&seas[row * EA_S + c] = v;
        }
        __syncthreads();

        // phase 1: E = ea @ [Wef|Wes]
#pragma unroll
        for (int h2i = 0; h2i < 2; h2i++) {
            float acc[8][4];
#pragma unroll
            for (int i = 0; i < 8; i++)
#pragma unroll
                for (int j = 0; j < 4; j++) acc[i][j] = 0.0f;
#pragma unroll
            for (int ks = 0; ks < 2; ks++) {
                int kb = ks * 16;
                unsigned a0 = *(const unsigned*)&seas[(erow0 + g) * EA_S + kb + 2 * tig];
                unsigned a1 = *(const unsigned*)&seas[(erow0 + g + 8) * EA_S + kb + 2 * tig];
                unsigned a2 = *(const unsigned*)&seas[(erow0 + g) * EA_S + kb + 2 * tig + 8];
                unsigned a3 = *(const unsigned*)&seas[(erow0 + g + 8) * EA_S + kb + 2 * tig + 8];
#pragma unroll
                for (int nt = 0; nt < 8; nt++) {
                    int col = col0 + h2i * 64 + nt * 8 + g;
                    unsigned b0 = *(const unsigned*)&wsT[col * WT_S + kb + 2 * tig];
                    unsigned b1 = *(const unsigned*)&wsT[col * WT_S + kb + 2 * tig + 8];
                    mma_f16(acc[nt], a0, a1, a2, a3, b0, b1);
                }
            }
#pragma unroll
            for (int nt = 0; nt < 8; nt++) {
                int c = col0 + h2i * 64 + nt * 8 + 2 * tig;
                *(half2*)&Eh[(erow0 + g) * EH_S + c]     = __floats2half2_rn(acc[nt][0], acc[nt][1]);
                *(half2*)&Eh[(erow0 + g + 8) * EH_S + c] = __floats2half2_rn(acc[nt][2], acc[nt][3]);
            }
        }
        __syncthreads();

        // phase 2: prefetch-8 gather, HADD2 sums, grouped flush
        {
            int srcs8[8], dsts8[8];
#pragma unroll
            for (int j = 0; j < 8; j++) {
                long e = e0 + w * 8 + j;
                srcs8[j] = srcs[e];
                dsts8[j] = dsts[e];
            }
            uint2 pbf[8], pbs[8];
#pragma unroll
            for (int j = 0; j < 8; j++) {
                size_t base = (size_t)srcs8[j] * 256 + lane * 4;
                pbf[j] = *(const uint2*)&PB[base];
                pbs[j] = *(const uint2*)&PB[base + 128];
            }
            int prev = -1;
            float4 acc = make_float4(0.f, 0.f, 0.f, 0.f);
            half2 af01, af23, as01, as23;
            af01 = af23 = as01 = as23 = __floats2half2_rn(0.f, 0.f);
#pragma unroll
            for (int j = 0; j < 8; j++) {
                int le = w * 8 + j;
                int dst = dsts8[j];
                if (dst != prev) {
                    if (prev >= 0)
                        red4(&agg[(size_t)prev * HID + lane * 4], acc);
                    acc = make_float4(0.f, 0.f, 0.f, 0.f);
                    size_t base = (size_t)dst * 256 + lane * 4;
                    uint2 pafu = *(const uint2*)&PA[base];
                    uint2 pasu = *(const uint2*)&PA[base + 128];
                    af01 = *(half2*)&pafu.x; af23 = *(half2*)&pafu.y;
                    as01 = *(half2*)&pasu.x; as23 = *(half2*)&pasu.y;
                    prev = dst;
                }
                uint2 efu = *(const uint2*)&Eh[le * EH_S + lane * 4];
                uint2 esu = *(const uint2*)&Eh[le * EH_S + 128 + lane * 4];

                half2 lf01 = __hadd2(__hadd2(*(half2*)&efu.x, af01), *(half2*)&pbf[j].x);
                half2 lf23 = __hadd2(__hadd2(*(half2*)&efu.y, af23), *(half2*)&pbf[j].y);
                half2 ls01 = __hadd2(__hadd2(*(half2*)&esu.x, as01), *(half2*)&pbs[j].x);
                half2 ls23 = __hadd2(__hadd2(*(half2*)&esu.y, as23), *(half2*)&pbs[j].y);

                float2 lf0 = __half22float2(lf01), lf1 = __half22float2(lf23);
                float2 ls0 = __half22float2(ls01), ls1 = __half22float2(ls23);

                acc.x += sigmoidf_(lf0.x) * softplusf_(ls0.x);
                acc.y += sigmoidf_(lf0.y) * softplusf_(ls0.y);
                acc.z += sigmoidf_(lf1.x) * softplusf_(ls1.x);
                acc.w += sigmoidf_(lf1.y) * softplusf_(ls1.y);
            }
            if (prev >= 0)
                red4(&agg[(size_t)prev * HID + lane * 4], acc);
        }
        __syncthreads();
    }
}

// ---------------- residual + relu (+ fp16 mirror) ----------------
__global__ void k_update(float* __restrict__ h, __half* __restrict__ hh,
                         const float* __restrict__ agg, int n) {
    int i = blockIdx.x * blockDim.x + threadIdx.x;
    int stride = gridDim.x * blockDim.x;
    for (; i < n; i += stride) {
        float v = fmaxf(h[i] + agg[i], 0.0f);
        h[i] = v;
        hh[i] = __float2half_rn(v);
    }
}

// ---------------- fused last update + pooling (batch sorted) ----------------
__global__ void k_update_pool(const float* __restrict__ h, const float* __restrict__ agg,
                              const int* __restrict__ batch,
                              float* __restrict__ pool, float* __restrict__ cnt) {
    const int NPB = 256;
    int n0 = blockIdx.x * NPB;
    if (n0 >= N_NODES) return;
    int c = threadIdx.x;  // 128
    float s = 0.0f;
    int cur = batch[n0];
    int mycnt = 0;
    for (int i = 0; i < NPB; i++) {
        int n = n0 + i;
        if (n >= N_NODES) break;
        int b = batch[n];
        if (b != cur) {
            atomicAdd(&pool[cur * HID + c], s);
            if (c == 0) atomicAdd(&cnt[cur], (float)mycnt);
            s = 0.0f; mycnt = 0; cur = b;
        }
        s += fmaxf(h[(size_t)n * HID + c] + agg[(size_t)n * HID + c], 0.0f);
        mycnt++;
    }
    atomicAdd(&pool[cur * HID + c], s);
    if (c == 0) atomicAdd(&cnt[cur], (float)mycnt);
}

// ---------------- head ----------------
__global__ void k_head(const float* __restrict__ pool, const float* __restrict__ cnt,
                       const float* __restrict__ W1, const float* __restrict__ b1,
                       const float* __restrict__ W2, const float* __restrict__ b2,
                       float* __restrict__ out) {
    int g = blockIdx.x;
    int c = threadIdx.x;
    __shared__ float p[128];
    __shared__ float t1[128];
    float invc = 1.0f / fmaxf(cnt[g], 1.0f);
    p[c] = pool[g * HID + c] * invc;
    __syncthreads();
    float v = b1[c];
#pragma unroll 16
    for (int k = 0; k < 128; k++) v += p[k] * W1[k * 128 + c];
    t1[c] = fmaxf(v, 0.0f);
    __syncthreads();
    if (c < 3) {
        float o = b2[c];
        for (int k = 0; k < 128; k++) o += t1[k] * W2[k * 3 + c];
        out[g * 3 + c] = o;
    }
}

// ---------------- launch ----------------
extern "C" void kernel_launch(void* const* d_in, const int* in_sizes, int n_in,
                              void* d_out, int out_size) {
    const float* x   = (const float*)d_in[0];
    const int*   ei  = (const int*)d_in[1];
    const float* ea  = (const float*)d_in[2];
    const int*   bat = (const int*)d_in[3];
    const float* Wf1 = (const float*)d_in[4];
    const float* bf1 = (const float*)d_in[5];
    const float* Ws1 = (const float*)d_in[6];
    const float* bs1 = (const float*)d_in[7];
    const float* Wp  = (const float*)d_in[8];
    const float* bp  = (const float*)d_in[9];
    const float* Wc[2]  = { (const float*)d_in[10], (const float*)d_in[14] };
    const float* bcf[2] = { (const float*)d_in[11], (const float*)d_in[15] };
    const float* Wsc[2] = { (const float*)d_in[12], (const float*)d_in[16] };
    const float* bcs[2] = { (const float*)d_in[13], (const float*)d_in[17] };
    const float* W1  = (const float*)d_in[18];
    const float* b1  = (const float*)d_in[19];
    const float* W2  = (const float*)d_in[20];
    const float* b2  = (const float*)d_in[21];
    float* out = (float*)d_out;

    float *pH, *pAgg, *pPool;
    __half *pPA, *pPB, *pHH, *pEAS;
    int *pDeg, *pCur, *pPart, *pSrcs, *pDsts;
    cudaGetSymbolAddress((void**)&pH,    g_h);
    cudaGetSymbolAddress((void**)&pHH,   g_hh);
    cudaGetSymbolAddress((void**)&pPA,   g_PA);
    cudaGetSymbolAddress((void**)&pPB,   g_PB);
    cudaGetSymbolAddress((void**)&pAgg,  g_agg);
    cudaGetSymbolAddress((void**)&pPool, g_pool);
    cudaGetSymbolAddress((void**)&pDeg,  g_deg);
    cudaGetSymbolAddress((void**)&pCur,  g_cursor);
    cudaGetSymbolAddress((void**)&pPart, g_part);
    cudaGetSymbolAddress((void**)&pSrcs, g_srcs);
    cudaGetSymbolAddress((void**)&pDsts, g_dsts);
    cudaGetSymbolAddress((void**)&pEAS,  g_eas);

    const int EDGE_SMEM = (256 * WT_S + 64 * EA_S + 64 * EH_S) * 2;
    const int PROJ_SMEM = 2 * 128 * PJ_S * 2;
    cudaFuncSetAttribute(k_edge_fused, cudaFuncAttributeMaxDynamicSharedMemorySize, EDGE_SMEM);
    cudaFuncSetAttribute(k_proj_all, cudaFuncAttributeMaxDynamicSharedMemorySize, PROJ_SMEM);

    // ---- build CSR + conv1 in one ea pass ----
    k_zero_int<<<128, 512>>>(pDeg, N_NODES);
    k_hist<<<N_EDGES / 256, 256>>>(ei, pDeg);
    k_scan_a<<<SCAN_NB, SCAN_B>>>(pDeg, pCur, pPart);
    k_scan_b<<<1, 256>>>(pPart, SCAN_NB);
    k_scan_c<<<SCAN_NB, SCAN_B>>>(pCur, pPart);
    k_zero<<<512, 256>>>(pAgg, N_NODES * 3);
    k_csr_conv1<<<N_EDGES / 256, 256>>>(x, ei, ea, Wf1, bf1, Ws1, bs1,
                                        pCur, pSrcs, pDsts, pEAS, pAgg);
    k_node1<<<N_NODES, 128>>>(x, pAgg, Wp, bp, pH, pHH);

    // ---- hidden convs ----
    k_zero<<<64, 256>>>(pPool, NGRAPH * HID + NGRAPH);
    for (int l = 0; l < 2; l++) {
        k_proj_all<<<(N_NODES + 127) / 128, 256, PROJ_SMEM>>>(
            pHH, Wc[l], Wsc[l], bcf[l], bcs[l], pPA, pPB);
        k_zero<<<2048, 256>>>(pAgg, N_NODES * HID);
        k_edge_fused<<<444, 256, EDGE_SMEM>>>(pSrcs, pDsts, pEAS, pPA, pPB,
                                              Wc[l], Wsc[l], pAgg);
        if (l == 0)
            k_update<<<2048, 256>>>(pH, pHH, pAgg, N_NODES * HID);
        else
            k_update_pool<<<(N_NODES + 255) / 256, 128>>>(pH, pAgg, bat,
                                                          pPool, pPool + NGRAPH * HID);
    }

    // ---- head ----
    k_head<<<NGRAPH, 128>>>(pPool, pPool + NGRAPH * HID, W1, b1, W2, b2, out);
}

// round 8
// speedup vs baseline: 1.3898x; 1.1343x over previous
#include <cuda_runtime.h>
#include <cuda_fp16.h>
#include <math.h>

#define N_NODES 100000
#define N_EDGES 1600000
#define HID 128
#define NGRAPH 64
#define ETILE 64
#define NTILES (N_EDGES / ETILE)
#define SCAN_B 512
#define SCAN_NB ((N_NODES + SCAN_B - 1) / SCAN_B)   // 196

// ---------------- device scratch ----------------
__device__ float  g_h[N_NODES * HID];
__device__ __half g_hh[N_NODES * HID];
__device__ __half g_PA[N_NODES * 256];
__device__ __half g_PB[N_NODES * 256];
__device__ float  g_agg[N_NODES * HID];
__device__ float  g_pool[NGRAPH * HID + NGRAPH];
__device__ int    g_deg[N_NODES];
__device__ int    g_cursor[N_NODES];
__device__ int    g_part[256];
__device__ int    g_srcs[N_EDGES];
__device__ int    g_dsts[N_EDGES];
__device__ __half g_eas[(size_t)N_EDGES * 32];

// ---------------- helpers ----------------
__device__ __forceinline__ float sigmoidf_(float x) { return 1.0f / (1.0f + __expf(-x)); }
__device__ __forceinline__ float softplusf_(float x) {
    return fmaxf(x, 0.0f) + __logf(1.0f + __expf(-fabsf(x)));
}
__device__ __forceinline__ float tanha_(float x) {
    float y;
    asm("tanh.approx.f32 %0, %1;" : "=f"(y) : "f"(x));
    return y;
}
__device__ __forceinline__ unsigned h2exp2_(unsigned x) {
    unsigned y;
    asm("ex2.approx.f16x2 %0, %1;" : "=r"(y) : "r"(x));
    return y;
}
__device__ __forceinline__ void red4(float* p, float4 v) {
    asm volatile("red.global.add.v4.f32 [%0], {%1,%2,%3,%4};"
                 :: "l"(p), "f"(v.x), "f"(v.y), "f"(v.z), "f"(v.w));
}
__device__ __forceinline__ void mma_f16(float d[4],
                                        unsigned a0, unsigned a1, unsigned a2, unsigned a3,
                                        unsigned b0, unsigned b1) {
    asm volatile("mma.sync.aligned.m16n8k16.row.col.f32.f16.f16.f32 "
                 "{%0,%1,%2,%3}, {%4,%5,%6,%7}, {%8,%9}, {%0,%1,%2,%3};\n"
                 : "+f"(d[0]), "+f"(d[1]), "+f"(d[2]), "+f"(d[3])
                 : "r"(a0), "r"(a1), "r"(a2), "r"(a3), "r"(b0), "r"(b1));
}

// ---------------- CSR build ----------------
__global__ void k_hist(const int* __restrict__ ei, int* __restrict__ deg) {
    int e = blockIdx.x * blockDim.x + threadIdx.x;
    if (e < N_EDGES) atomicAdd(&deg[ei[N_EDGES + e]], 1);
}
__global__ void k_scan_a(const int* __restrict__ deg, int* __restrict__ cursor,
                         int* __restrict__ part) {
    __shared__ int s[SCAN_B];
    int i = blockIdx.x * SCAN_B + threadIdx.x;
    int v = (i < N_NODES) ? deg[i] : 0;
    s[threadIdx.x] = v;
    __syncthreads();
    for (int off = 1; off < SCAN_B; off <<= 1) {
        int t = (threadIdx.x >= off) ? s[threadIdx.x - off] : 0;
        __syncthreads();
        s[threadIdx.x] += t;
        __syncthreads();
    }
    if (i < N_NODES) cursor[i] = s[threadIdx.x] - v;   // exclusive within block
    if (threadIdx.x == SCAN_B - 1) part[blockIdx.x] = s[threadIdx.x];
}
__global__ void k_scan_b(int* __restrict__ part, int nb) {
    __shared__ int s[256];
    int v = (threadIdx.x < nb) ? part[threadIdx.x] : 0;
    s[threadIdx.x] = v;
    __syncthreads();
    for (int off = 1; off < 256; off <<= 1) {
        int t = (threadIdx.x >= off) ? s[threadIdx.x - off] : 0;
        __syncthreads();
        s[threadIdx.x] += t;
        __syncthreads();
    }
    if (threadIdx.x < nb) part[threadIdx.x] = s[threadIdx.x] - v;  // exclusive
}

// ---------------- fused CSR scatter + conv1 (single ea pass, scan_c folded in) ----------------
__global__ void k_csr_conv1(const float* __restrict__ x, const int* __restrict__ ei,
                            const float* __restrict__ ea,
                            const float* __restrict__ Wf, const float* __restrict__ bf,
                            const float* __restrict__ Ws, const float* __restrict__ bs,
                            int* __restrict__ cursor, const int* __restrict__ part,
                            int* __restrict__ srcs, int* __restrict__ dsts,
                            __half* __restrict__ eas, float* __restrict__ agg) {
    __shared__ float sWf[38 * 3], sWs[38 * 3], sbf[3], sbs[3];
    int t = threadIdx.x;
    if (t < 114) { sWf[t] = Wf[t]; sWs[t] = Ws[t]; }
    if (t < 3)   { sbf[t] = bf[t]; sbs[t] = bs[t]; }
    __syncthreads();
    int e = blockIdx.x * blockDim.x + t;
    if (e >= N_EDGES) return;
    int src = ei[e];
    int dst = ei[N_EDGES + e];

    float z[38];
    z[0] = x[dst * 3 + 0]; z[1] = x[dst * 3 + 1]; z[2] = x[dst * 3 + 2];
    z[3] = x[src * 3 + 0]; z[4] = x[src * 3 + 1]; z[5] = x[src * 3 + 2];
    float4 v[8];
    const float4* s = (const float4*)&ea[(size_t)e * 32];
#pragma unroll
    for (int j = 0; j < 8; j++) {
        v[j] = s[j];
        z[6 + j * 4 + 0] = v[j].x; z[6 + j * 4 + 1] = v[j].y;
        z[6 + j * 4 + 2] = v[j].z; z[6 + j * 4 + 3] = v[j].w;
    }
#pragma unroll
    for (int c = 0; c < 3; c++) {
        float lf = sbf[c], ls = sbs[c];
#pragma unroll
        for (int k = 0; k < 38; k++) {
            lf += z[k] * sWf[k * 3 + c];
            ls += z[k] * sWs[k * 3 + c];
        }
        float m = sigmoidf_(lf) * softplusf_(ls);
        atomicAdd(&agg[dst * 3 + c], m);
    }
    int pos = atomicAdd(&cursor[dst], 1) + part[dst >> 9];  // SCAN_B = 512
    srcs[pos] = src;
    dsts[pos] = dst;
    __half* d = &eas[(size_t)pos * 32];
#pragma unroll
    for (int j = 0; j < 8; j++) {
        *(half2*)&d[j * 4]     = __floats2half2_rn(v[j].x, v[j].y);
        *(half2*)&d[j * 4 + 2] = __floats2half2_rn(v[j].z, v[j].w);
    }
}

// ---------------- node projection after conv1 ----------------
__global__ void k_node1(const float* __restrict__ x, const float* __restrict__ agg,
                        const float* __restrict__ Wp, const float* __restrict__ bp,
                        float* __restrict__ h, __half* __restrict__ hh) {
    int n = blockIdx.x;
    int c = threadIdx.x;
    __shared__ float sx[3];
    if (c < 3) sx[c] = x[n * 3 + c] + agg[n * 3 + c];
    __syncthreads();
    float v = bp[c] + sx[0] * Wp[c] + sx[1] * Wp[128 + c] + sx[2] * Wp[256 + c];
    v = fmaxf(v, 0.0f);
    h[n * HID + c] = v;
    hh[n * HID + c] = __float2half_rn(v);
}

// ---------------- fused 4-part node projection (stage h ONCE) ----------------
#define PJ_S 136
__global__ __launch_bounds__(256, 3) void k_proj_all(
        const __half* __restrict__ hh,
        const float* __restrict__ Wf, const float* __restrict__ Ws,
        const float* __restrict__ bf, const float* __restrict__ bs,
        __half* __restrict__ PA, __half* __restrict__ PB) {
    extern __shared__ __half psm[];
    __half* hs  = psm;                 // [128 rows][136]
    __half* wsT = psm + 128 * PJ_S;    // [128 cols][136 k]

    int t = threadIdx.x;
    int lane = t & 31;
    int w = t >> 5;
    int g = lane >> 2;
    int tig = lane & 3;
    int n0 = blockIdx.x * 128;

#pragma unroll
    for (int j = 0; j < 8; j++) {
        int idx = t + j * 256;
        int row = idx >> 4;
        int c = (idx & 15) * 8;
        uint4 v = make_uint4(0, 0, 0, 0);
        int n = n0 + row;
        if (n < N_NODES) v = *(const uint4*)&hh[(size_t)n * 128 + c];
        *(uint4*)&hs[row * PJ_S + c] = v;
    }

    int r0 = w * 16;
#pragma unroll 1
    for (int part = 0; part < 4; part++) {
        const float* W; const float* bias; __half* out; int coloff;
        if (part == 0)      { W = Wf;             bias = bf;      out = PA; coloff = 0;   }
        else if (part == 1) { W = Ws;             bias = bs;      out = PA; coloff = 128; }
        else if (part == 2) { W = Wf + 128 * 128; bias = nullptr; out = PB; coloff = 0;   }
        else                { W = Ws + 128 * 128; bias = nullptr; out = PB; coloff = 128; }

        __syncthreads();
#pragma unroll
        for (int j = 0; j < 16; j++) {
            int idx4 = t + j * 256;
            int k = idx4 >> 5;
            int c = (idx4 & 31) * 4;
            float4 v = *(const float4*)&W[k * 128 + c];
            wsT[(c + 0) * PJ_S + k] = __float2half_rn(v.x);
            wsT[(c + 1) * PJ_S + k] = __float2half_rn(v.y);
            wsT[(c + 2) * PJ_S + k] = __float2half_rn(v.z);
            wsT[(c + 3) * PJ_S + k] = __float2half_rn(v.w);
        }
        __syncthreads();

#pragma unroll
        for (int h2i = 0; h2i < 2; h2i++) {
            float acc[8][4];
#pragma unroll
            for (int i = 0; i < 8; i++)
#pragma unroll
                for (int j = 0; j < 4; j++) acc[i][j] = 0.0f;
#pragma unroll
            for (int kb8 = 0; kb8 < 8; kb8++) {
                int kb = kb8 * 16;
                unsigned a0 = *(const unsigned*)&hs[(r0 + g) * PJ_S + kb + 2 * tig];
                unsigned a1 = *(const unsigned*)&hs[(r0 + g + 8) * PJ_S + kb + 2 * tig];
                unsigned a2 = *(const unsigned*)&hs[(r0 + g) * PJ_S + kb + 2 * tig + 8];
                unsigned a3 = *(const unsigned*)&hs[(r0 + g + 8) * PJ_S + kb + 2 * tig + 8];
#pragma unroll
                for (int nt = 0; nt < 8; nt++) {
                    int col = h2i * 64 + nt * 8 + g;
                    unsigned b0 = *(const unsigned*)&wsT[col * PJ_S + kb + 2 * tig];
                    unsigned b1 = *(const unsigned*)&wsT[col * PJ_S + kb + 2 * tig + 8];
                    mma_f16(acc[nt], a0, a1, a2, a3, b0, b1);
                }
            }
#pragma unroll
            for (int nt = 0; nt < 8; nt++) {
                int c = h2i * 64 + nt * 8 + 2 * tig;
                float b0 = 0.f, b1 = 0.f;
                if (bias) { b0 = bias[c]; b1 = bias[c + 1]; }
                int n = n0 + r0 + g;
                if (n < N_NODES)
                    *(half2*)&out[(size_t)n * 256 + coloff + c] =
                        __floats2half2_rn(acc[nt][0] + b0, acc[nt][1] + b1);
                n = n0 + r0 + g + 8;
                if (n < N_NODES)
                    *(half2*)&out[(size_t)n * 256 + coloff + c] =
                        __floats2half2_rn(acc[nt][2] + b0, acc[nt][3] + b1);
            }
        }
    }
}

// ---------------- fused edge kernel over CSR-sorted edges ----------------
#define WT_S 40
#define EA_S 40
#define EH_S 264
__global__ __launch_bounds__(256, 3) void k_edge_fused(
        const int* __restrict__ srcs, const int* __restrict__ dsts,
        const __half* __restrict__ eas,
        const __half* __restrict__ PA, const __half* __restrict__ PB,
        const float* __restrict__ Wf, const float* __restrict__ Ws,
        float* __restrict__ agg) {
    extern __shared__ __half sm[];
    __half* wsT  = sm;
    __half* seas = sm + 256 * WT_S;
    __half* Eh   = sm + 256 * WT_S + 64 * EA_S;

    int t = threadIdx.x;
    int lane = t & 31;
    int w = t >> 5;
    int g = lane >> 2;
    int tig = lane & 3;

#pragma unroll
    for (int j = 0; j < 32; j++) {
        int idx = t + j * 256;
        int k = idx >> 8;
        int c = idx & 255;
        float v = (c < 128) ? Wf[(256 + k) * 128 + c]
                            : Ws[(256 + k) * 128 + (c - 128)];
        wsT[c * WT_S + k] = __float2half_rn(v);
    }
    __syncthreads();

    int erow0 = (w & 3) * 16;
    int col0 = (w >> 2) * 128;
    const half2 nl2e = __floats2half2_rn(-1.44269504f, -1.44269504f);

    for (int tile = blockIdx.x; tile < NTILES; tile += gridDim.x) {
        long e0 = (long)tile * ETILE;
        {
            uint4 v = *(const uint4*)&eas[e0 * 32 + t * 8];
            int row = t >> 2;
            int c = (t & 3) * 8;
            *(uint4*)&seas[row * EA_S + c] = v;
        }
        __syncthreads();

        // phase 1: E = ea @ [Wef|Wes]
#pragma unroll
        for (int h2i = 0; h2i < 2; h2i++) {
            float acc[8][4];
#pragma unroll
            for (int i = 0; i < 8; i++)
#pragma unroll
                for (int j = 0; j < 4; j++) acc[i][j] = 0.0f;
#pragma unroll
            for (int ks = 0; ks < 2; ks++) {
                int kb = ks * 16;
                unsigned a0 = *(const unsigned*)&seas[(erow0 + g) * EA_S + kb + 2 * tig];
                unsigned a1 = *(const unsigned*)&seas[(erow0 + g + 8) * EA_S + kb + 2 * tig];
                unsigned a2 = *(const unsigned*)&seas[(erow0 + g) * EA_S + kb + 2 * tig + 8];
                unsigned a3 = *(const unsigned*)&seas[(erow0 + g + 8) * EA_S + kb + 2 * tig + 8];
#pragma unroll
                for (int nt = 0; nt < 8; nt++) {
                    int col = col0 + h2i * 64 + nt * 8 + g;
                    unsigned b0 = *(const unsigned*)&wsT[col * WT_S + kb + 2 * tig];
                    unsigned b1 = *(const unsigned*)&wsT[col * WT_S + kb + 2 * tig + 8];
                    mma_f16(acc[nt], a0, a1, a2, a3, b0, b1);
                }
            }
#pragma unroll
            for (int nt = 0; nt < 8; nt++) {
                int c = col0 + h2i * 64 + nt * 8 + 2 * tig;
                *(half2*)&Eh[(erow0 + g) * EH_S + c]     = __floats2half2_rn(acc[nt][0], acc[nt][1]);
                *(half2*)&Eh[(erow0 + g + 8) * EH_S + c] = __floats2half2_rn(acc[nt][2], acc[nt][3]);
            }
        }
        __syncthreads();

        // phase 2: prefetch-8 gather, reduced-MUFU gating, grouped flush
        {
            int srcs8[8], dsts8[8];
#pragma unroll
            for (int j = 0; j < 8; j++) {
                long e = e0 + w * 8 + j;
                srcs8[j] = srcs[e];
                dsts8[j] = dsts[e];
            }
            uint2 pbf[8], pbs[8];
#pragma unroll
            for (int j = 0; j < 8; j++) {
                size_t base = (size_t)srcs8[j] * 256 + lane * 4;
                pbf[j] = *(const uint2*)&PB[base];
                pbs[j] = *(const uint2*)&PB[base + 128];
            }
            int prev = -1;
            float4 acc = make_float4(0.f, 0.f, 0.f, 0.f);
            half2 af01, af23, as01, as23;
            af01 = af23 = as01 = as23 = __floats2half2_rn(0.f, 0.f);
#pragma unroll
            for (int j = 0; j < 8; j++) {
                int le = w * 8 + j;
                int dst = dsts8[j];
                if (dst != prev) {
                    if (prev >= 0)
                        red4(&agg[(size_t)prev * HID + lane * 4], acc);
                    acc = make_float4(0.f, 0.f, 0.f, 0.f);
                    size_t base = (size_t)dst * 256 + lane * 4;
                    uint2 pafu = *(const uint2*)&PA[base];
                    uint2 pasu = *(const uint2*)&PA[base + 128];
                    af01 = *(half2*)&pafu.x; af23 = *(half2*)&pafu.y;
                    as01 = *(half2*)&pasu.x; as23 = *(half2*)&pasu.y;
                    prev = dst;
                }
                uint2 efu = *(const uint2*)&Eh[le * EH_S + lane * 4];
                uint2 esu = *(const uint2*)&Eh[le * EH_S + 128 + lane * 4];

                half2 lf01 = __hadd2(__hadd2(*(half2*)&efu.x, af01), *(half2*)&pbf[j].x);
                half2 lf23 = __hadd2(__hadd2(*(half2*)&efu.y, af23), *(half2*)&pbf[j].y);
                half2 ls01 = __hadd2(__hadd2(*(half2*)&esu.x, as01), *(half2*)&pbs[j].x);
                half2 ls23 = __hadd2(__hadd2(*(half2*)&esu.y, as23), *(half2*)&pbs[j].y);

                // t = exp(-|s|) via packed ex2 (result in (0,1], fp16-safe)
                half2 e01 = __hmul2(__habs2(ls01), nl2e);
                half2 e23 = __hmul2(__habs2(ls23), nl2e);
                unsigned tu01 = h2exp2_(*(unsigned*)&e01);
                unsigned tu23 = h2exp2_(*(unsigned*)&e23);

                float2 f0 = __half22float2(lf01), f1 = __half22float2(lf23);
                float2 s0 = __half22float2(ls01), s1 = __half22float2(ls23);
                float2 t0 = __half22float2(*(half2*)&tu01), t1 = __half22float2(*(half2*)&tu23);

                // sigmoid(f) = 0.5*tanh(f/2) + 0.5  (1 MUFU per channel)
                float sg0 = fmaf(tanha_(0.5f * f0.x), 0.5f, 0.5f);
                float sg1 = fmaf(tanha_(0.5f * f0.y), 0.5f, 0.5f);
                float sg2 = fmaf(tanha_(0.5f * f1.x), 0.5f, 0.5f);
                float sg3 = fmaf(tanha_(0.5f * f1.y), 0.5f, 0.5f);

                // softplus(s) = max(s,0) + log(1 + exp(-|s|))
                float sp0 = fmaxf(s0.x, 0.f) + __logf(1.f + t0.x);
                float sp1 = fmaxf(s0.y, 0.f) + __logf(1.f + t0.y);
                float sp2 = fmaxf(s1.x, 0.f) + __logf(1.f + t1.x);
                float sp3 = fmaxf(s1.y, 0.f) + __logf(1.f + t1.y);

                acc.x = fmaf(sg0, sp0, acc.x);
                acc.y = fmaf(sg1, sp1, acc.y);
                acc.z = fmaf(sg2, sp2, acc.z);
                acc.w = fmaf(sg3, sp3, acc.w);
            }
            if (prev >= 0)
                red4(&agg[(size_t)prev * HID + lane * 4], acc);
        }
        __syncthreads();
    }
}

// ---------------- residual + relu (+ fp16 mirror) ----------------
__global__ void k_update(float* __restrict__ h, __half* __restrict__ hh,
                         const float* __restrict__ agg, int n) {
    int i = blockIdx.x * blockDim.x + threadIdx.x;
    int stride = gridDim.x * blockDim.x;
    for (; i < n; i += stride) {
        float v = fmaxf(h[i] + agg[i], 0.0f);
        h[i] = v;
        hh[i] = __float2half_rn(v);
    }
}

// ---------------- fused last update + pooling (batch sorted) ----------------
__global__ void k_update_pool(const float* __restrict__ h, const float* __restrict__ agg,
                              const int* __restrict__ batch,
                              float* __restrict__ pool, float* __restrict__ cnt) {
    const int NPB = 256;
    int n0 = blockIdx.x * NPB;
    if (n0 >= N_NODES) return;
    int c = threadIdx.x;  // 128
    float s = 0.0f;
    int cur = batch[n0];
    int mycnt = 0;
    for (int i = 0; i < NPB; i++) {
        int n = n0 + i;
        if (n >= N_NODES) break;
        int b = batch[n];
        if (b != cur) {
            atomicAdd(&pool[cur * HID + c], s);
            if (c == 0) atomicAdd(&cnt[cur], (float)mycnt);
            s = 0.0f; mycnt = 0; cur = b;
        }
        s += fmaxf(h[(size_t)n * HID + c] + agg[(size_t)n * HID + c], 0.0f);
        mycnt++;
    }
    atomicAdd(&pool[cur * HID + c], s);
    if (c == 0) atomicAdd(&cnt[cur], (float)mycnt);
}

// ---------------- head ----------------
__global__ void k_head(const float* __restrict__ pool, const float* __restrict__ cnt,
                       const float* __restrict__ W1, const float* __restrict__ b1,
                       const float* __restrict__ W2, const float* __restrict__ b2,
                       float* __restrict__ out) {
    int g = blockIdx.x;
    int c = threadIdx.x;
    __shared__ float p[128];
    __shared__ float t1[128];
    float invc = 1.0f / fmaxf(cnt[g], 1.0f);
    p[c] = pool[g * HID + c] * invc;
    __syncthreads();
    float v = b1[c];
#pragma unroll 16
    for (int k = 0; k < 128; k++) v += p[k] * W1[k * 128 + c];
    t1[c] = fmaxf(v, 0.0f);
    __syncthreads();
    if (c < 3) {
        float o = b2[c];
        for (int k = 0; k < 128; k++) o += t1[k] * W2[k * 3 + c];
        out[g * 3 + c] = o;
    }
}

// ---------------- launch ----------------
extern "C" void kernel_launch(void* const* d_in, const int* in_sizes, int n_in,
                              void* d_out, int out_size) {
    const float* x   = (const float*)d_in[0];
    const int*   ei  = (const int*)d_in[1];
    const float* ea  = (const float*)d_in[2];
    const int*   bat = (const int*)d_in[3];
    const float* Wf1 = (const float*)d_in[4];
    const float* bf1 = (const float*)d_in[5];
    const float* Ws1 = (const float*)d_in[6];
    const float* bs1 = (const float*)d_in[7];
    const float* Wp  = (const float*)d_in[8];
    const float* bp  = (const float*)d_in[9];
    const float* Wc[2]  = { (const float*)d_in[10], (const float*)d_in[14] };
    const float* bcf[2] = { (const float*)d_in[11], (const float*)d_in[15] };
    const float* Wsc[2] = { (const float*)d_in[12], (const float*)d_in[16] };
    const float* bcs[2] = { (const float*)d_in[13], (const float*)d_in[17] };
    const float* W1  = (const float*)d_in[18];
    const float* b1  = (const float*)d_in[19];
    const float* W2  = (const float*)d_in[20];
    const float* b2  = (const float*)d_in[21];
    float* out = (float*)d_out;

    float *pH, *pAgg, *pPool;
    __half *pPA, *pPB, *pHH, *pEAS;
    int *pDeg, *pCur, *pPart, *pSrcs, *pDsts;
    cudaGetSymbolAddress((void**)&pH,    g_h);
    cudaGetSymbolAddress((void**)&pHH,   g_hh);
    cudaGetSymbolAddress((void**)&pPA,   g_PA);
    cudaGetSymbolAddress((void**)&pPB,   g_PB);
    cudaGetSymbolAddress((void**)&pAgg,  g_agg);
    cudaGetSymbolAddress((void**)&pPool, g_pool);
    cudaGetSymbolAddress((void**)&pDeg,  g_deg);
    cudaGetSymbolAddress((void**)&pCur,  g_cursor);
    cudaGetSymbolAddress((void**)&pPart, g_part);
    cudaGetSymbolAddress((void**)&pSrcs, g_srcs);
    cudaGetSymbolAddress((void**)&pDsts, g_dsts);
    cudaGetSymbolAddress((void**)&pEAS,  g_eas);

    const int EDGE_SMEM = (256 * WT_S + 64 * EA_S + 64 * EH_S) * 2;
    const int PROJ_SMEM = 2 * 128 * PJ_S * 2;
    cudaFuncSetAttribute(k_edge_fused, cudaFuncAttributeMaxDynamicSharedMemorySize, EDGE_SMEM);
    cudaFuncSetAttribute(k_proj_all, cudaFuncAttributeMaxDynamicSharedMemorySize, PROJ_SMEM);

    // ---- zeroing via graph memset nodes (not kernels) ----
    cudaMemsetAsync(pDeg, 0, N_NODES * sizeof(int));
    cudaMemsetAsync(pAgg, 0, N_NODES * 3 * sizeof(float));
    cudaMemsetAsync(pPool, 0, (NGRAPH * HID + NGRAPH) * sizeof(float));

    // ---- build CSR + conv1 ----
    k_hist<<<N_EDGES / 256, 256>>>(ei, pDeg);
    k_scan_a<<<SCAN_NB, SCAN_B>>>(pDeg, pCur, pPart);
    k_scan_b<<<1, 256>>>(pPart, SCAN_NB);
    k_csr_conv1<<<N_EDGES / 256, 256>>>(x, ei, ea, Wf1, bf1, Ws1, bs1,
                                        pCur, pPart, pSrcs, pDsts, pEAS, pAgg);
    k_node1<<<N_NODES, 128>>>(x, pAgg, Wp, bp, pH, pHH);

    // ---- hidden convs ----
    for (int l = 0; l < 2; l++) {
        k_proj_all<<<(N_NODES + 127) / 128, 256, PROJ_SMEM>>>(
            pHH, Wc[l], Wsc[l], bcf[l], bcs[l], pPA, pPB);
        cudaMemsetAsync(pAgg, 0, (size_t)N_NODES * HID * sizeof(float));
        k_edge_fused<<<444, 256, EDGE_SMEM>>>(pSrcs, pDsts, pEAS, pPA, pPB,
                                              Wc[l], Wsc[l], pAgg);
        if (l == 0)
            k_update<<<2048, 256>>>(pH, pHH, pAgg, N_NODES * HID);
        else
            k_update_pool<<<(N_NODES + 255) / 256, 128>>>(pH, pAgg, bat,
                                                          pPool, pPool + NGRAPH * HID);
    }

    // ---- head ----
    k_head<<<NGRAPH, 128>>>(pPool, pPool + NGRAPH * HID, W1, b1, W2, b2, out);
}

// round 9
// speedup vs baseline: 1.4417x; 1.0373x over previous
#include <cuda_runtime.h>
#include <cuda_fp16.h>
#include <math.h>

#define N_NODES 100000
#define N_EDGES 1600000
#define HID 128
#define NGRAPH 64
#define ETILE 64
#define NTILES (N_EDGES / ETILE)
#define SCAN_B 512
#define SCAN_NB ((N_NODES + SCAN_B - 1) / SCAN_B)   // 196

// ---------------- device scratch ----------------
__device__ float  g_h[N_NODES * HID];
__device__ __half g_hh[N_NODES * HID];
__device__ __half g_PA[N_NODES * 256];
__device__ __half g_PB[N_NODES * 256];
__device__ float  g_agg[N_NODES * HID];
__device__ float  g_pool[NGRAPH * HID + NGRAPH];
__device__ int    g_deg[N_NODES];
__device__ int    g_cursor[N_NODES];
__device__ int    g_part[256];
__device__ int4   g_esd[N_EDGES];          // {src, dst, e, 0} in sorted position
__device__ int    g_srcs[N_EDGES];
__device__ int    g_dsts[N_EDGES];
__device__ __half g_eas[(size_t)N_EDGES * 32];

// ---------------- helpers ----------------
__device__ __forceinline__ float sigmoidf_(float x) { return 1.0f / (1.0f + __expf(-x)); }
__device__ __forceinline__ float softplusf_(float x) {
    return fmaxf(x, 0.0f) + __logf(1.0f + __expf(-fabsf(x)));
}
__device__ __forceinline__ float tanha_(float x) {
    float y;
    asm("tanh.approx.f32 %0, %1;" : "=f"(y) : "f"(x));
    return y;
}
__device__ __forceinline__ unsigned h2exp2_(unsigned x) {
    unsigned y;
    asm("ex2.approx.f16x2 %0, %1;" : "=r"(y) : "r"(x));
    return y;
}
__device__ __forceinline__ void red4(float* p, float4 v) {
    asm volatile("red.global.add.v4.f32 [%0], {%1,%2,%3,%4};"
                 :: "l"(p), "f"(v.x), "f"(v.y), "f"(v.z), "f"(v.w));
}
__device__ __forceinline__ void mma_f16(float d[4],
                                        unsigned a0, unsigned a1, unsigned a2, unsigned a3,
                                        unsigned b0, unsigned b1) {
    asm volatile("mma.sync.aligned.m16n8k16.row.col.f32.f16.f16.f32 "
                 "{%0,%1,%2,%3}, {%4,%5,%6,%7}, {%8,%9}, {%0,%1,%2,%3};\n"
                 : "+f"(d[0]), "+f"(d[1]), "+f"(d[2]), "+f"(d[3])
                 : "r"(a0), "r"(a1), "r"(a2), "r"(a3), "r"(b0), "r"(b1));
}

// ---------------- CSR build ----------------
__global__ void k_hist(const int* __restrict__ ei, int* __restrict__ deg) {
    int e = blockIdx.x * blockDim.x + threadIdx.x;
    if (e < N_EDGES) atomicAdd(&deg[ei[N_EDGES + e]], 1);
}
__global__ void k_scan_a(const int* __restrict__ deg, int* __restrict__ cursor,
                         int* __restrict__ part) {
    __shared__ int s[SCAN_B];
    int i = blockIdx.x * SCAN_B + threadIdx.x;
    int v = (i < N_NODES) ? deg[i] : 0;
    s[threadIdx.x] = v;
    __syncthreads();
    for (int off = 1; off < SCAN_B; off <<= 1) {
        int t = (threadIdx.x >= off) ? s[threadIdx.x - off] : 0;
        __syncthreads();
        s[threadIdx.x] += t;
        __syncthreads();
    }
    if (i < N_NODES) cursor[i] = s[threadIdx.x] - v;   // exclusive within block
    if (threadIdx.x == SCAN_B - 1) part[blockIdx.x] = s[threadIdx.x];
}
__global__ void k_scan_b(int* __restrict__ part, int nb) {
    __shared__ int s[256];
    int v = (threadIdx.x < nb) ? part[threadIdx.x] : 0;
    s[threadIdx.x] = v;
    __syncthreads();
    for (int off = 1; off < 256; off <<= 1) {
        int t = (threadIdx.x >= off) ? s[threadIdx.x - off] : 0;
        __syncthreads();
        s[threadIdx.x] += t;
        __syncthreads();
    }
    if (threadIdx.x < nb) part[threadIdx.x] = s[threadIdx.x] - v;  // exclusive
}

// ---------------- pass 1: conv1 + light permutation scatter ----------------
__global__ void k_conv1_perm(const float* __restrict__ x, const int* __restrict__ ei,
                             const float* __restrict__ ea,
                             const float* __restrict__ Wf, const float* __restrict__ bf,
                             const float* __restrict__ Ws, const float* __restrict__ bs,
                             int* __restrict__ cursor, const int* __restrict__ part,
                             int4* __restrict__ esd, float* __restrict__ agg) {
    __shared__ float sWf[38 * 3], sWs[38 * 3], sbf[3], sbs[3];
    int t = threadIdx.x;
    if (t < 114) { sWf[t] = Wf[t]; sWs[t] = Ws[t]; }
    if (t < 3)   { sbf[t] = bf[t]; sbs[t] = bs[t]; }
    __syncthreads();
    int e = blockIdx.x * blockDim.x + t;
    if (e >= N_EDGES) return;
    int src = ei[e];
    int dst = ei[N_EDGES + e];

    float z[38];
    z[0] = x[dst * 3 + 0]; z[1] = x[dst * 3 + 1]; z[2] = x[dst * 3 + 2];
    z[3] = x[src * 3 + 0]; z[4] = x[src * 3 + 1]; z[5] = x[src * 3 + 2];
    const float4* s = (const float4*)&ea[(size_t)e * 32];
#pragma unroll
    for (int j = 0; j < 8; j++) {
        float4 v = s[j];
        z[6 + j * 4 + 0] = v.x; z[6 + j * 4 + 1] = v.y;
        z[6 + j * 4 + 2] = v.z; z[6 + j * 4 + 3] = v.w;
    }
#pragma unroll
    for (int c = 0; c < 3; c++) {
        float lf = sbf[c], ls = sbs[c];
#pragma unroll
        for (int k = 0; k < 38; k++) {
            lf += z[k] * sWf[k * 3 + c];
            ls += z[k] * sWs[k * 3 + c];
        }
        float m = sigmoidf_(lf) * softplusf_(ls);
        atomicAdd(&agg[dst * 3 + c], m);
    }
    int pos = atomicAdd(&cursor[dst], 1) + part[dst >> 9];  // SCAN_B = 512
    esd[pos] = make_int4(src, dst, e, 0);                   // 16 B scatter
}

// ---------------- pass 2: coalesced gather-convert into sorted order ----------------
__global__ void k_gather(const int4* __restrict__ esd, const float* __restrict__ ea,
                         int* __restrict__ srcs, int* __restrict__ dsts,
                         __half* __restrict__ eas) {
    int p = blockIdx.x * blockDim.x + threadIdx.x;
    if (p >= N_EDGES) return;
    int4 v = esd[p];
    srcs[p] = v.x;
    dsts[p] = v.y;
    const float4* s = (const float4*)&ea[(size_t)v.z * 32];   // full 128B line
    __half* d = &eas[(size_t)p * 32];
#pragma unroll
    for (int j = 0; j < 4; j++) {
        float4 a = s[j * 2];
        float4 b = s[j * 2 + 1];
        half2 h0 = __floats2half2_rn(a.x, a.y);
        half2 h1 = __floats2half2_rn(a.z, a.w);
        half2 h2 = __floats2half2_rn(b.x, b.y);
        half2 h3 = __floats2half2_rn(b.z, b.w);
        uint4 pk;
        pk.x = *(unsigned*)&h0; pk.y = *(unsigned*)&h1;
        pk.z = *(unsigned*)&h2; pk.w = *(unsigned*)&h3;
        *(uint4*)&d[j * 8] = pk;
    }
}

// ---------------- node projection after conv1 (grid-stride) ----------------
__global__ void k_node1(const float* __restrict__ x, const float* __restrict__ agg,
                        const float* __restrict__ Wp, const float* __restrict__ bp,
                        float* __restrict__ h, __half* __restrict__ hh) {
    int i = blockIdx.x * blockDim.x + threadIdx.x;
    int stride = gridDim.x * blockDim.x;
    for (; i < N_NODES * HID; i += stride) {
        int n = i >> 7;
        int c = i & 127;
        float s0 = x[n * 3 + 0] + agg[n * 3 + 0];
        float s1 = x[n * 3 + 1] + agg[n * 3 + 1];
        float s2 = x[n * 3 + 2] + agg[n * 3 + 2];
        float v = bp[c] + s0 * Wp[c] + s1 * Wp[128 + c] + s2 * Wp[256 + c];
        v = fmaxf(v, 0.0f);
        h[i] = v;
        hh[i] = __float2half_rn(v);
    }
}

// ---------------- fused 4-part node projection (stage h ONCE) ----------------
#define PJ_S 136
__global__ __launch_bounds__(256, 3) void k_proj_all(
        const __half* __restrict__ hh,
        const float* __restrict__ Wf, const float* __restrict__ Ws,
        const float* __restrict__ bf, const float* __restrict__ bs,
        __half* __restrict__ PA, __half* __restrict__ PB) {
    extern __shared__ __half psm[];
    __half* hs  = psm;                 // [128 rows][136]
    __half* wsT = psm + 128 * PJ_S;    // [128 cols][136 k]

    int t = threadIdx.x;
    int lane = t & 31;
    int w = t >> 5;
    int g = lane >> 2;
    int tig = lane & 3;
    int n0 = blockIdx.x * 128;

#pragma unroll
    for (int j = 0; j < 8; j++) {
        int idx = t + j * 256;
        int row = idx >> 4;
        int c = (idx & 15) * 8;
        uint4 v = make_uint4(0, 0, 0, 0);
        int n = n0 + row;
        if (n < N_NODES) v = *(const uint4*)&hh[(size_t)n * 128 + c];
        *(uint4*)&hs[row * PJ_S + c] = v;
    }

    int r0 = w * 16;
#pragma unroll 1
    for (int part = 0; part < 4; part++) {
        const float* W; const float* bias; __half* out; int coloff;
        if (part == 0)      { W = Wf;             bias = bf;      out = PA; coloff = 0;   }
        else if (part == 1) { W = Ws;             bias = bs;      out = PA; coloff = 128; }
        else if (part == 2) { W = Wf + 128 * 128; bias = nullptr; out = PB; coloff = 0;   }
        else                { W = Ws + 128 * 128; bias = nullptr; out = PB; coloff = 128; }

        __syncthreads();
#pragma unroll
        for (int j = 0; j < 16; j++) {
            int idx4 = t + j * 256;
            int k = idx4 >> 5;
            int c = (idx4 & 31) * 4;
            float4 v = *(const float4*)&W[k * 128 + c];
            wsT[(c + 0) * PJ_S + k] = __float2half_rn(v.x);
            wsT[(c + 1) * PJ_S + k] = __float2half_rn(v.y);
            wsT[(c + 2) * PJ_S + k] = __float2half_rn(v.z);
            wsT[(c + 3) * PJ_S + k] = __float2half_rn(v.w);
        }
        __syncthreads();

#pragma unroll
        for (int h2i = 0; h2i < 2; h2i++) {
            float acc[8][4];
#pragma unroll
            for (int i = 0; i < 8; i++)
#pragma unroll
                for (int j = 0; j < 4; j++) acc[i][j] = 0.0f;
#pragma unroll
            for (int kb8 = 0; kb8 < 8; kb8++) {
                int kb = kb8 * 16;
                unsigned a0 = *(const unsigned*)&hs[(r0 + g) * PJ_S + kb + 2 * tig];
                unsigned a1 = *(const unsigned*)&hs[(r0 + g + 8) * PJ_S + kb + 2 * tig];
                unsigned a2 = *(const unsigned*)&hs[(r0 + g) * PJ_S + kb + 2 * tig + 8];
                unsigned a3 = *(const unsigned*)&hs[(r0 + g + 8) * PJ_S + kb + 2 * tig + 8];
#pragma unroll
                for (int nt = 0; nt < 8; nt++) {
                    int col = h2i * 64 + nt * 8 + g;
                    unsigned b0 = *(const unsigned*)&wsT[col * PJ_S + kb + 2 * tig];
                    unsigned b1 = *(const unsigned*)&wsT[col * PJ_S + kb + 2 * tig + 8];
                    mma_f16(acc[nt], a0, a1, a2, a3, b0, b1);
                }
            }
#pragma unroll
            for (int nt = 0; nt < 8; nt++) {
                int c = h2i * 64 + nt * 8 + 2 * tig;
                float b0 = 0.f, b1 = 0.f;
                if (bias) { b0 = bias[c]; b1 = bias[c + 1]; }
                int n = n0 + r0 + g;
                if (n < N_NODES)
                    *(half2*)&out[(size_t)n * 256 + coloff + c] =
                        __floats2half2_rn(acc[nt][0] + b0, acc[nt][1] + b1);
                n = n0 + r0 + g + 8;
                if (n < N_NODES)
                    *(half2*)&out[(size_t)n * 256 + coloff + c] =
                        __floats2half2_rn(acc[nt][2] + b0, acc[nt][3] + b1);
            }
        }
    }
}

// ---------------- fused edge kernel over CSR-sorted edges ----------------
#define WT_S 40
#define EA_S 40
#define EH_S 264
__global__ __launch_bounds__(256, 3) void k_edge_fused(
        const int* __restrict__ srcs, const int* __restrict__ dsts,
        const __half* __restrict__ eas,
        const __half* __restrict__ PA, const __half* __restrict__ PB,
        const float* __restrict__ Wf, const float* __restrict__ Ws,
        float* __restrict__ agg) {
    extern __shared__ __half sm[];
    __half* wsT  = sm;
    __half* seas = sm + 256 * WT_S;
    __half* Eh   = sm + 256 * WT_S + 64 * EA_S;

    int t = threadIdx.x;
    int lane = t & 31;
    int w = t >> 5;
    int g = lane >> 2;
    int tig = lane & 3;

#pragma unroll
    for (int j = 0; j < 32; j++) {
        int idx = t + j * 256;
        int k = idx >> 8;
        int c = idx & 255;
        float v = (c < 128) ? Wf[(256 + k) * 128 + c]
                            : Ws[(256 + k) * 128 + (c - 128)];
        wsT[c * WT_S + k] = __float2half_rn(v);
    }
    __syncthreads();

    int erow0 = (w & 3) * 16;
    int col0 = (w >> 2) * 128;
    const half2 nl2e = __floats2half2_rn(-1.44269504f, -1.44269504f);

    for (int tile = blockIdx.x; tile < NTILES; tile += gridDim.x) {
        long e0 = (long)tile * ETILE;
        {
            uint4 v = *(const uint4*)&eas[e0 * 32 + t * 8];
            int row = t >> 2;
            int c = (t & 3) * 8;
            *(uint4*)&seas[row * EA_S + c] = v;
        }
        __syncthreads();

        // phase 1: E = ea @ [Wef|Wes]
#pragma unroll
        for (int h2i = 0; h2i < 2; h2i++) {
            float acc[8][4];
#pragma unroll
            for (int i = 0; i < 8; i++)
#pragma unroll
                for (int j = 0; j < 4; j++) acc[i][j] = 0.0f;
#pragma unroll
            for (int ks = 0; ks < 2; ks++) {
                int kb = ks * 16;
                unsigned a0 = *(const unsigned*)&seas[(erow0 + g) * EA_S + kb + 2 * tig];
                unsigned a1 = *(const unsigned*)&seas[(erow0 + g + 8) * EA_S + kb + 2 * tig];
                unsigned a2 = *(const unsigned*)&seas[(erow0 + g) * EA_S + kb + 2 * tig + 8];
                unsigned a3 = *(const unsigned*)&seas[(erow0 + g + 8) * EA_S + kb + 2 * tig + 8];
#pragma unroll
                for (int nt = 0; nt < 8; nt++) {
                    int col = col0 + h2i * 64 + nt * 8 + g;
                    unsigned b0 = *(const unsigned*)&wsT[col * WT_S + kb + 2 * tig];
                    unsigned b1 = *(const unsigned*)&wsT[col * WT_S + kb + 2 * tig + 8];
                    mma_f16(acc[nt], a0, a1, a2, a3, b0, b1);
                }
            }
#pragma unroll
            for (int nt = 0; nt < 8; nt++) {
                int c = col0 + h2i * 64 + nt * 8 + 2 * tig;
                *(half2*)&Eh[(erow0 + g) * EH_S + c]     = __floats2half2_rn(acc[nt][0], acc[nt][1]);
                *(half2*)&Eh[(erow0 + g + 8) * EH_S + c] = __floats2half2_rn(acc[nt][2], acc[nt][3]);
            }
        }
        __syncthreads();

        // phase 2: prefetch-8 gather, reduced-MUFU gating, grouped flush
        {
            int srcs8[8], dsts8[8];
#pragma unroll
            for (int j = 0; j < 8; j++) {
                long e = e0 + w * 8 + j;
                srcs8[j] = srcs[e];
                dsts8[j] = dsts[e];
            }
            uint2 pbf[8], pbs[8];
#pragma unroll
            for (int j = 0; j < 8; j++) {
                size_t base = (size_t)srcs8[j] * 256 + lane * 4;
                pbf[j] = *(const uint2*)&PB[base];
                pbs[j] = *(const uint2*)&PB[base + 128];
            }
            int prev = -1;
            float4 acc = make_float4(0.f, 0.f, 0.f, 0.f);
            half2 af01, af23, as01, as23;
            af01 = af23 = as01 = as23 = __floats2half2_rn(0.f, 0.f);
#pragma unroll
            for (int j = 0; j < 8; j++) {
                int le = w * 8 + j;
                int dst = dsts8[j];
                if (dst != prev) {
                    if (prev >= 0)
                        red4(&agg[(size_t)prev * HID + lane * 4], acc);
                    acc = make_float4(0.f, 0.f, 0.f, 0.f);
                    size_t base = (size_t)dst * 256 + lane * 4;
                    uint2 pafu = *(const uint2*)&PA[base];
                    uint2 pasu = *(const uint2*)&PA[base + 128];
                    af01 = *(half2*)&pafu.x; af23 = *(half2*)&pafu.y;
                    as01 = *(half2*)&pasu.x; as23 = *(half2*)&pasu.y;
                    prev = dst;
                }
                uint2 efu = *(const uint2*)&Eh[le * EH_S + lane * 4];
                uint2 esu = *(const uint2*)&Eh[le * EH_S + 128 + lane * 4];

                half2 lf01 = __hadd2(__hadd2(*(half2*)&efu.x, af01), *(half2*)&pbf[j].x);
                half2 lf23 = __hadd2(__hadd2(*(half2*)&efu.y, af23), *(half2*)&pbf[j].y);
                half2 ls01 = __hadd2(__hadd2(*(half2*)&esu.x, as01), *(half2*)&pbs[j].x);
                half2 ls23 = __hadd2(__hadd2(*(half2*)&esu.y, as23), *(half2*)&pbs[j].y);

                half2 e01 = __hmul2(__habs2(ls01), nl2e);
                half2 e23 = __hmul2(__habs2(ls23), nl2e);
                unsigned tu01 = h2exp2_(*(unsigned*)&e01);
                unsigned tu23 = h2exp2_(*(unsigned*)&e23);

                float2 f0 = __half22float2(lf01), f1 = __half22float2(lf23);
                float2 s0 = __half22float2(ls01), s1 = __half22float2(ls23);
                float2 t0 = __half22float2(*(half2*)&tu01), t1 = __half22float2(*(half2*)&tu23);

                float sg0 = fmaf(tanha_(0.5f * f0.x), 0.5f, 0.5f);
                float sg1 = fmaf(tanha_(0.5f * f0.y), 0.5f, 0.5f);
                float sg2 = fmaf(tanha_(0.5f * f1.x), 0.5f, 0.5f);
                float sg3 = fmaf(tanha_(0.5f * f1.y), 0.5f, 0.5f);

                float sp0 = fmaxf(s0.x, 0.f) + __logf(1.f + t0.x);
                float sp1 = fmaxf(s0.y, 0.f) + __logf(1.f + t0.y);
                float sp2 = fmaxf(s1.x, 0.f) + __logf(1.f + t1.x);
                float sp3 = fmaxf(s1.y, 0.f) + __logf(1.f + t1.y);

                acc.x = fmaf(sg0, sp0, acc.x);
                acc.y = fmaf(sg1, sp1, acc.y);
                acc.z = fmaf(sg2, sp2, acc.z);
                acc.w = fmaf(sg3, sp3, acc.w);
            }
            if (prev >= 0)
                red4(&agg[(size_t)prev * HID + lane * 4], acc);
        }
        __syncthreads();
    }
}

// ---------------- residual + relu (+ fp16 mirror) ----------------
__global__ void k_update(float* __restrict__ h, __half* __restrict__ hh,
                         const float* __restrict__ agg, int n) {
    int i = blockIdx.x * blockDim.x + threadIdx.x;
    int stride = gridDim.x * blockDim.x;
    for (; i < n; i += stride) {
        float v = fmaxf(h[i] + agg[i], 0.0f);
        h[i] = v;
        hh[i] = __float2half_rn(v);
    }
}

// ---------------- fused last update + pooling (batch sorted) ----------------
__global__ void k_update_pool(const float* __restrict__ h, const float* __restrict__ agg,
                              const int* __restrict__ batch,
                              float* __restrict__ pool, float* __restrict__ cnt) {
    const int NPB = 256;
    int n0 = blockIdx.x * NPB;
    if (n0 >= N_NODES) return;
    int c = threadIdx.x;  // 128
    float s = 0.0f;
    int cur = batch[n0];
    int mycnt = 0;
    for (int i = 0; i < NPB; i++) {
        int n = n0 + i;
        if (n >= N_NODES) break;
        int b = batch[n];
        if (b != cur) {
            atomicAdd(&pool[cur * HID + c], s);
            if (c == 0) atomicAdd(&cnt[cur], (float)mycnt);
            s = 0.0f; mycnt = 0; cur = b;
        }
        s += fmaxf(h[(size_t)n * HID + c] + agg[(size_t)n * HID + c], 0.0f);
        mycnt++;
    }
    atomicAdd(&pool[cur * HID + c], s);
    if (c == 0) atomicAdd(&cnt[cur], (float)mycnt);
}

// ---------------- head ----------------
__global__ void k_head(const float* __restrict__ pool, const float* __restrict__ cnt,
                       const float* __restrict__ W1, const float* __restrict__ b1,
                       const float* __restrict__ W2, const float* __restrict__ b2,
                       float* __restrict__ out) {
    int g = blockIdx.x;
    int c = threadIdx.x;
    __shared__ float p[128];
    __shared__ float t1[128];
    float invc = 1.0f / fmaxf(cnt[g], 1.0f);
    p[c] = pool[g * HID + c] * invc;
    __syncthreads();
    float v = b1[c];
#pragma unroll 16
    for (int k = 0; k < 128; k++) v += p[k] * W1[k * 128 + c];
    t1[c] = fmaxf(v, 0.0f);
    __syncthreads();
    if (c < 3) {
        float o = b2[c];
        for (int k = 0; k < 128; k++) o += t1[k] * W2[k * 3 + c];
        out[g * 3 + c] = o;
    }
}

// ---------------- launch ----------------
extern "C" void kernel_launch(void* const* d_in, const int* in_sizes, int n_in,
                              void* d_out, int out_size) {
    const float* x   = (const float*)d_in[0];
    const int*   ei  = (const int*)d_in[1];
    const float* ea  = (const float*)d_in[2];
    const int*   bat = (const int*)d_in[3];
    const float* Wf1 = (const float*)d_in[4];
    const float* bf1 = (const float*)d_in[5];
    const float* Ws1 = (const float*)d_in[6];
    const float* bs1 = (const float*)d_in[7];
    const float* Wp  = (const float*)d_in[8];
    const float* bp  = (const float*)d_in[9];
    const float* Wc[2]  = { (const float*)d_in[10], (const float*)d_in[14] };
    const float* bcf[2] = { (const float*)d_in[11], (const float*)d_in[15] };
    const float* Wsc[2] = { (const float*)d_in[12], (const float*)d_in[16] };
    const float* bcs[2] = { (const float*)d_in[13], (const float*)d_in[17] };
    const float* W1  = (const float*)d_in[18];
    const float* b1  = (const float*)d_in[19];
    const float* W2  = (const float*)d_in[20];
    const float* b2  = (const float*)d_in[21];
    float* out = (float*)d_out;

    float *pH, *pAgg, *pPool;
    __half *pPA, *pPB, *pHH, *pEAS;
    int *pDeg, *pCur, *pPart, *pSrcs, *pDsts;
    int4 *pEsd;
    cudaGetSymbolAddress((void**)&pH,    g_h);
    cudaGetSymbolAddress((void**)&pHH,   g_hh);
    cudaGetSymbolAddress((void**)&pPA,   g_PA);
    cudaGetSymbolAddress((void**)&pPB,   g_PB);
    cudaGetSymbolAddress((void**)&pAgg,  g_agg);
    cudaGetSymbolAddress((void**)&pPool, g_pool);
    cudaGetSymbolAddress((void**)&pDeg,  g_deg);
    cudaGetSymbolAddress((void**)&pCur,  g_cursor);
    cudaGetSymbolAddress((void**)&pPart, g_part);
    cudaGetSymbolAddress((void**)&pEsd,  g_esd);
    cudaGetSymbolAddress((void**)&pSrcs, g_srcs);
    cudaGetSymbolAddress((void**)&pDsts, g_dsts);
    cudaGetSymbolAddress((void**)&pEAS,  g_eas);

    const int EDGE_SMEM = (256 * WT_S + 64 * EA_S + 64 * EH_S) * 2;
    const int PROJ_SMEM = 2 * 128 * PJ_S * 2;
    cudaFuncSetAttribute(k_edge_fused, cudaFuncAttributeMaxDynamicSharedMemorySize, EDGE_SMEM);
    cudaFuncSetAttribute(k_proj_all, cudaFuncAttributeMaxDynamicSharedMemorySize, PROJ_SMEM);

    // ---- zeroing via graph memset nodes ----
    cudaMemsetAsync(pDeg, 0, N_NODES * sizeof(int));
    cudaMemsetAsync(pAgg, 0, N_NODES * 3 * sizeof(float));
    cudaMemsetAsync(pPool, 0, (NGRAPH * HID + NGRAPH) * sizeof(float));

    // ---- build CSR + conv1 (two-pass: light scatter then coalesced gather) ----
    k_hist<<<N_EDGES / 256, 256>>>(ei, pDeg);
    k_scan_a<<<SCAN_NB, SCAN_B>>>(pDeg, pCur, pPart);
    k_scan_b<<<1, 256>>>(pPart, SCAN_NB);
    k_conv1_perm<<<N_EDGES / 256, 256>>>(x, ei, ea, Wf1, bf1, Ws1, bs1,
                                         pCur, pPart, pEsd, pAgg);
    k_gather<<<N_EDGES / 256, 256>>>(pEsd, ea, pSrcs, pDsts, pEAS);
    k_node1<<<592, 256>>>(x, pAgg, Wp, bp, pH, pHH);

    // ---- hidden convs ----
    for (int l = 0; l < 2; l++) {
        k_proj_all<<<(N_NODES + 127) / 128, 256, PROJ_SMEM>>>(
            pHH, Wc[l], Wsc[l], bcf[l], bcs[l], pPA, pPB);
        cudaMemsetAsync(pAgg, 0, (size_t)N_NODES * HID * sizeof(float));
        k_edge_fused<<<444, 256, EDGE_SMEM>>>(pSrcs, pDsts, pEAS, pPA, pPB,
                                              Wc[l], Wsc[l], pAgg);
        if (l == 0)
            k_update<<<2048, 256>>>(pH, pHH, pAgg, N_NODES * HID);
        else
            k_update_pool<<<(N_NODES + 255) / 256, 128>>>(pH, pAgg, bat,
                                                          pPool, pPool + NGRAPH * HID);
    }

    // ---- head ----
    k_head<<<NGRAPH, 128>>>(pPool, pPool + NGRAPH * HID, W1, b1, W2, b2, out);
}